// round 7
// baseline (speedup 1.0000x reference)
#include <cuda_runtime.h>
#include <cstdint>

// InterAttention (ESIM-style) on GB300 — tf32 mma.sync, 128x256 CTA / 64x64 warp tiles.
// (tcgen05 is unavailable: harness ptxas targets sm_103 without the 'a' suffix.)
//   r1m = lrelu(lrelu(r1@W1+b1)@W2+b2)*m1
//   S   = r1m @ r2m^T + (-1e10 where !(m1&m2))
//   o1  = softmax_rows(S)*mpos ; o2 = softmax_cols(S)*mpos
//   r1c = o1 @ r2m ; r2c = o2^T @ r1m
//   out = lrelu(lrelu([xm|xc]@Wc1+bc1)@Wc2+bc2)*mask

#define NEG_INF_F (-1e10f)
#define SLOPE 0.01f
#define Bc 64
#define Lc 512
#define Dc 512
#define BLD (Bc*Lc*Dc)

// ---- scratch (static device memory) ----
__device__ float g_h[BLD];
__device__ float g_r1m[BLD];
__device__ float g_r2m[BLD];
__device__ float g_r1mT[BLD];
__device__ float g_r2mT[BLD];
__device__ float g_S[BLD];
__device__ float g_o1[BLD];
__device__ float g_o2T[BLD];
__device__ float g_c1[BLD];
__device__ float g_c2[BLD];
__device__ float g_W1T[Dc*Dc];
__device__ float g_W2T[Dc*Dc];
__device__ float g_Wc1T[2*Dc*Dc];
__device__ float g_Wc2T[Dc*Dc];

__device__ __forceinline__ float to_tf32(float x) {
    float r;
    asm("cvt.rna.tf32.f32 %0, %1;" : "=f"(r) : "f"(x));
    return r;
}

__device__ __forceinline__ void mma_tf32(float* c, const uint32_t* a, const uint32_t* b) {
    asm volatile(
        "mma.sync.aligned.m16n8k8.row.col.f32.tf32.tf32.f32 "
        "{%0,%1,%2,%3}, {%4,%5,%6,%7}, {%8,%9}, {%0,%1,%2,%3};"
        : "+f"(c[0]), "+f"(c[1]), "+f"(c[2]), "+f"(c[3])
        : "r"(a[0]), "r"(a[1]), "r"(a[2]), "r"(a[3]), "r"(b[0]), "r"(b[1]));
}

// ---------------- tf32 GEMM ----------------
// C[b][m][n] = epilogue( sum_k opA[b][m][k] * opB[b][n][k] )
// A: [M][K] row-major (K contiguous), optional concat with A2 at Ksplit.
// B: [N][K] row-major (K contiguous).
// mode 0: plain; 1: +bias, lrelu, *rowmask; 2: additive -inf mask from m1/m2.
#define BM 128
#define BN 256
#define BKK 16
#define SPAD 4
#define SW (BKK + SPAD)   // 20 floats
// dynamic SMEM: As[2][BM][SW] + Bs[2][BN][SW]
#define AS_FLOATS (2*BM*SW)                  // 5120
#define GSMEM ((AS_FLOATS + 2*BN*SW) * 4)    // 61440 bytes

__global__ __launch_bounds__(256, 1)
void gemm_tf32(const float* __restrict__ A, const float* __restrict__ A2,
               const float* __restrict__ B, float* __restrict__ C,
               int M, int N, int K, int Ksplit,
               int ldA, int ldA2, int ldB, int ldC,
               long sA, long sA2, long sB, long sC,
               const float* __restrict__ bias,
               const int* __restrict__ rowmask,
               const int* __restrict__ m1p, const int* __restrict__ m2p,
               int mode)
{
    extern __shared__ float sm[];
    float* Asm = sm;                 // [2][BM][SW]
    float* Bsm = sm + AS_FLOATS;     // [2][BN][SW]

    const int b = blockIdx.z;
    const float* Ab  = A  + (long)b * sA;
    const float* A2b = A2 + (long)b * sA2;
    const float* Bb  = B  + (long)b * sB;
    float*       Cb  = C  + (long)b * sC;

    const int tid = threadIdx.x;
    const int mBlock = blockIdx.y * BM;
    const int nBlock = blockIdx.x * BN;

    // A tile load: 128 rows x 16 k, 2 threads/row (8 floats each)
    const int arow = tid >> 1;
    const int acol = (tid & 1) * 8;
    // B tile load: 256 rows x 16 k, 1 thread/row (16 floats)
    const int brow = tid;

    // warp mapping: 8 warps 2(m) x 4(n); warp tile 64x64
    const int warp = tid >> 5, lane = tid & 31;
    const int mw = (warp >> 2) * 64;
    const int nw = (warp & 3) * 64;
    const int gr = lane >> 2;     // 0..7
    const int tg = lane & 3;      // 0..3

    float acc[4][8][4];
#pragma unroll
    for (int i = 0; i < 4; i++)
#pragma unroll
        for (int j = 0; j < 8; j++)
#pragma unroll
            for (int q = 0; q < 4; q++) acc[i][j][q] = 0.0f;

    const int KT = K / BKK;
    float4 ra0, ra1, rb[4];

    auto do_ldg = [&](int k0) {
        const float* Ap; int kb, ld;
        if (k0 < Ksplit) { Ap = Ab;  kb = k0;          ld = ldA;  }
        else             { Ap = A2b; kb = k0 - Ksplit; ld = ldA2; }
        const float* pa = Ap + (long)(mBlock + arow) * ld + kb + acol;
        ra0 = *(const float4*)(pa);
        ra1 = *(const float4*)(pa + 4);
        const float* pb = Bb + (long)(nBlock + brow) * ldB + k0;
#pragma unroll
        for (int c = 0; c < 4; c++) rb[c] = *(const float4*)(pb + c * 4);
    };
    auto cvt4 = [](float4 v) {
        v.x = to_tf32(v.x); v.y = to_tf32(v.y); v.z = to_tf32(v.z); v.w = to_tf32(v.w);
        return v;
    };
    auto do_sts = [&](int s) {
        float* ap = Asm + (s * BM + arow) * SW + acol;
        *(float4*)(ap)     = cvt4(ra0);
        *(float4*)(ap + 4) = cvt4(ra1);
        float* bp = Bsm + (s * BN + brow) * SW;
#pragma unroll
        for (int c = 0; c < 4; c++) *(float4*)(bp + c * 4) = cvt4(rb[c]);
    };

    do_ldg(0);
    do_sts(0);
    __syncthreads();

    for (int kt = 0; kt < KT; kt++) {
        const int buf = kt & 1;
        if (kt + 1 < KT) do_ldg((kt + 1) * BKK);

        const float* Ai = Asm + (buf * BM) * SW;
        const float* Bi = Bsm + (buf * BN) * SW;
#pragma unroll
        for (int ks = 0; ks < 2; ks++) {
            const int kb = ks * 8;
            uint32_t af[4][4], bf[8][2];
#pragma unroll
            for (int mt = 0; mt < 4; mt++) {
                const int mr = mw + mt * 16;
                af[mt][0] = __float_as_uint(Ai[(mr + gr)     * SW + kb + tg]);
                af[mt][1] = __float_as_uint(Ai[(mr + gr + 8) * SW + kb + tg]);
                af[mt][2] = __float_as_uint(Ai[(mr + gr)     * SW + kb + tg + 4]);
                af[mt][3] = __float_as_uint(Ai[(mr + gr + 8) * SW + kb + tg + 4]);
            }
#pragma unroll
            for (int nt = 0; nt < 8; nt++) {
                const int nr = nw + nt * 8 + gr;
                bf[nt][0] = __float_as_uint(Bi[nr * SW + kb + tg]);
                bf[nt][1] = __float_as_uint(Bi[nr * SW + kb + tg + 4]);
            }
#pragma unroll
            for (int mt = 0; mt < 4; mt++)
#pragma unroll
                for (int nt = 0; nt < 8; nt++)
                    mma_tf32(acc[mt][nt], af[mt], bf[nt]);
        }

        if (kt + 1 < KT) do_sts((kt + 1) & 1);
        __syncthreads();
    }

    // ---- epilogue ----
#pragma unroll
    for (int mt = 0; mt < 4; mt++) {
        const int r0 = mBlock + mw + mt * 16 + gr;
#pragma unroll
        for (int half = 0; half < 2; half++) {
            const int row = r0 + half * 8;
            float rm = 1.0f; int mi = 1;
            if (mode == 1 && rowmask) rm = rowmask[(long)b * M + row] ? 1.0f : 0.0f;
            if (mode == 2) mi = m1p[(long)b * M + row];
#pragma unroll
            for (int nt = 0; nt < 8; nt++) {
                const int c0 = nBlock + nw + nt * 8 + tg * 2;
                float v0 = acc[mt][nt][half * 2 + 0];
                float v1 = acc[mt][nt][half * 2 + 1];
                if (mode == 1) {
                    v0 += bias[c0];     v1 += bias[c0 + 1];
                    v0 = (v0 >= 0.0f) ? v0 : SLOPE * v0;
                    v1 = (v1 >= 0.0f) ? v1 : SLOPE * v1;
                    v0 *= rm; v1 *= rm;
                } else if (mode == 2) {
                    const int mj0 = m2p[(long)b * N + c0];
                    const int mj1 = m2p[(long)b * N + c0 + 1];
                    v0 += (mi && mj0) ? 0.0f : NEG_INF_F;
                    v1 += (mi && mj1) ? 0.0f : NEG_INF_F;
                }
                float2 o; o.x = v0; o.y = v1;
                *(float2*)&Cb[(long)row * ldC + c0] = o;
            }
        }
    }
}

// ---------------- batched transpose ----------------
__global__ __launch_bounds__(256)
void transpose_kernel(const float* __restrict__ src, float* __restrict__ dst,
                      int rows, int cols, long sS, long sD)
{
    __shared__ float t[32][33];
    const float* s = src + (long)blockIdx.z * sS;
    float* d       = dst + (long)blockIdx.z * sD;
    const int x0 = blockIdx.x * 32;
    const int y0 = blockIdx.y * 32;
    const int tx = threadIdx.x, ty = threadIdx.y;
#pragma unroll
    for (int j = ty; j < 32; j += 8)
        t[j][tx] = s[(long)(y0 + j) * cols + x0 + tx];
    __syncthreads();
#pragma unroll
    for (int j = ty; j < 32; j += 8)
        d[(long)(x0 + j) * rows + y0 + tx] = t[tx][j];
}

// ---------------- Row softmax ----------------
__global__ __launch_bounds__(256)
void softmax_row_kernel(const float* __restrict__ S, float* __restrict__ O,
                        const int* __restrict__ m1, const int* __restrict__ m2)
{
    const int b = blockIdx.y, i = blockIdx.x;
    const float* row = S + ((long)b * Lc + i) * Lc;
    float* orow      = O + ((long)b * Lc + i) * Lc;
    const int tid = threadIdx.x;

    float v0 = row[tid], v1 = row[tid + 256];
    __shared__ float red[256];

    red[tid] = fmaxf(v0, v1);
    __syncthreads();
    for (int s = 128; s > 0; s >>= 1) {
        if (tid < s) red[tid] = fmaxf(red[tid], red[tid + s]);
        __syncthreads();
    }
    float mx = red[0];
    __syncthreads();

    float e0 = __expf(v0 - mx), e1 = __expf(v1 - mx);
    red[tid] = e0 + e1;
    __syncthreads();
    for (int s = 128; s > 0; s >>= 1) {
        if (tid < s) red[tid] += red[tid + s];
        __syncthreads();
    }
    float inv = 1.0f / red[0];

    int mi = m1[b * Lc + i];
    float f0 = (mi && m2[b * Lc + tid])       ? 1.0f : 0.0f;
    float f1 = (mi && m2[b * Lc + tid + 256]) ? 1.0f : 0.0f;
    orow[tid]       = e0 * inv * f0;
    orow[tid + 256] = e1 * inv * f1;
}

// -------- Column softmax, writes TRANSPOSED result --------
__global__ __launch_bounds__(1024)
void softmax_col_kernel(const float* __restrict__ S, float* __restrict__ OT,
                        const int* __restrict__ m1, const int* __restrict__ m2)
{
    const int b  = blockIdx.y;
    const int tx = threadIdx.x, ty = threadIdx.y;   // 32x32
    const int j  = blockIdx.x * 32 + tx;
    const float* Sb = S  + (long)b * Lc * Lc;
    float* OTb      = OT + (long)b * Lc * Lc;

    float vals[16];
    float lmax = -1e30f;
#pragma unroll
    for (int it = 0; it < 16; it++) {
        int i = ty + it * 32;
        vals[it] = Sb[(long)i * Lc + j];
        lmax = fmaxf(lmax, vals[it]);
    }
    __shared__ float red[32][33];
    red[ty][tx] = lmax;
    __syncthreads();
    for (int s = 16; s > 0; s >>= 1) {
        if (ty < s) red[ty][tx] = fmaxf(red[ty][tx], red[ty + s][tx]);
        __syncthreads();
    }
    float mx = red[0][tx];
    __syncthreads();

    float lsum = 0.0f;
#pragma unroll
    for (int it = 0; it < 16; it++) {
        vals[it] = __expf(vals[it] - mx);
        lsum += vals[it];
    }
    red[ty][tx] = lsum;
    __syncthreads();
    for (int s = 16; s > 0; s >>= 1) {
        if (ty < s) red[ty][tx] += red[ty + s][tx];
        __syncthreads();
    }
    float inv = 1.0f / red[0][tx];
    __syncthreads();

    const int mj = m2[b * Lc + j];
    const int j0 = blockIdx.x * 32;
#pragma unroll
    for (int it = 0; it < 16; it++) {
        int i = ty + it * 32;
        float f = (mj && m1[b * Lc + i]) ? 1.0f : 0.0f;
        float v = vals[it] * inv * f;
        red[ty][tx] = v;
        __syncthreads();
        OTb[(long)(j0 + ty) * Lc + it * 32 + tx] = red[tx][ty];
        __syncthreads();
    }
}

// ---------------- Launch ----------------
extern "C" void kernel_launch(void* const* d_in, const int* in_sizes, int n_in,
                              void* d_out, int out_size)
{
    const float* r1    = (const float*)d_in[0];
    const float* r2    = (const float*)d_in[1];
    const int*   mask1 = (const int*)  d_in[2];
    const int*   mask2 = (const int*)  d_in[3];
    const float* W1    = (const float*)d_in[4];
    const float* b1    = (const float*)d_in[5];
    const float* W2    = (const float*)d_in[6];
    const float* b2    = (const float*)d_in[7];
    const float* Wc1   = (const float*)d_in[8];   // [1024, 512]
    const float* bc1   = (const float*)d_in[9];
    const float* Wc2   = (const float*)d_in[10];
    const float* bc2   = (const float*)d_in[11];
    float* out = (float*)d_out;

    float *h, *r1m, *r2m, *r1mT, *r2mT, *S, *o1, *o2T, *c1, *c2;
    float *W1T, *W2T, *Wc1T, *Wc2T;
    cudaGetSymbolAddress((void**)&h,    g_h);
    cudaGetSymbolAddress((void**)&r1m,  g_r1m);
    cudaGetSymbolAddress((void**)&r2m,  g_r2m);
    cudaGetSymbolAddress((void**)&r1mT, g_r1mT);
    cudaGetSymbolAddress((void**)&r2mT, g_r2mT);
    cudaGetSymbolAddress((void**)&S,    g_S);
    cudaGetSymbolAddress((void**)&o1,   g_o1);
    cudaGetSymbolAddress((void**)&o2T,  g_o2T);
    cudaGetSymbolAddress((void**)&c1,   g_c1);
    cudaGetSymbolAddress((void**)&c2,   g_c2);
    cudaGetSymbolAddress((void**)&W1T,  g_W1T);
    cudaGetSymbolAddress((void**)&W2T,  g_W2T);
    cudaGetSymbolAddress((void**)&Wc1T, g_Wc1T);
    cudaGetSymbolAddress((void**)&Wc2T, g_Wc2T);

    cudaFuncSetAttribute(gemm_tf32, cudaFuncAttributeMaxDynamicSharedMemorySize, GSMEM);

    const long LD = (long)Lc * Dc;   // 262144
    dim3 blk(256);
    dim3 gridMlp(Dc / BN, (Bc * Lc) / BM, 1);   // (2, 256, 1)
    dim3 gridBat(Dc / BN, Lc / BM, Bc);         // (2, 4, 64)
    dim3 tblk(32, 8);

    // ---- transpose weights ----
    transpose_kernel<<<dim3(Dc/32, Dc/32, 1), tblk>>>(W1,  W1T,  Dc,   Dc, 0, 0);
    transpose_kernel<<<dim3(Dc/32, Dc/32, 1), tblk>>>(W2,  W2T,  Dc,   Dc, 0, 0);
    transpose_kernel<<<dim3(Dc/32, 2*Dc/32, 1), tblk>>>(Wc1, Wc1T, 2*Dc, Dc, 0, 0);
    transpose_kernel<<<dim3(Dc/32, Dc/32, 1), tblk>>>(Wc2, Wc2T, Dc,   Dc, 0, 0);

    // ---- MLP r1 ----
    gemm_tf32<<<gridMlp, blk, GSMEM>>>(r1, r1, W1T, h,
        Bc*Lc, Dc, Dc, Dc, Dc, Dc, Dc, Dc, 0, 0, 0, 0,
        b1, nullptr, nullptr, nullptr, 1);
    gemm_tf32<<<gridMlp, blk, GSMEM>>>(h, h, W2T, r1m,
        Bc*Lc, Dc, Dc, Dc, Dc, Dc, Dc, Dc, 0, 0, 0, 0,
        b2, mask1, nullptr, nullptr, 1);
    // ---- MLP r2 ----
    gemm_tf32<<<gridMlp, blk, GSMEM>>>(r2, r2, W1T, h,
        Bc*Lc, Dc, Dc, Dc, Dc, Dc, Dc, Dc, 0, 0, 0, 0,
        b1, nullptr, nullptr, nullptr, 1);
    gemm_tf32<<<gridMlp, blk, GSMEM>>>(h, h, W2T, r2m,
        Bc*Lc, Dc, Dc, Dc, Dc, Dc, Dc, Dc, 0, 0, 0, 0,
        b2, mask2, nullptr, nullptr, 1);

    // ---- Scores: S = r1m @ r2m^T + mask ----
    gemm_tf32<<<dim3(Lc/BN, Lc/BM, Bc), blk, GSMEM>>>(r1m, r1m, r2m, S,
        Lc, Lc, Dc, Dc, Dc, Dc, Dc, Lc, LD, LD, LD, LD,
        nullptr, nullptr, mask1, mask2, 2);

    // ---- Softmaxes ----
    softmax_col_kernel<<<dim3(Lc/32, Bc), dim3(32, 32)>>>(S, o2T, mask1, mask2);
    softmax_row_kernel<<<dim3(Lc, Bc), 256>>>(S, o1, mask1, mask2);

    // ---- transpose activations for value GEMMs ----
    transpose_kernel<<<dim3(Dc/32, Lc/32, Bc), tblk>>>(r1m, r1mT, Lc, Dc, LD, LD);
    transpose_kernel<<<dim3(Dc/32, Lc/32, Bc), tblk>>>(r2m, r2mT, Lc, Dc, LD, LD);

    // ---- r1c = o1 @ r2m ----
    gemm_tf32<<<gridBat, blk, GSMEM>>>(o1, o1, r2mT, c1,
        Lc, Dc, Lc, Lc, Lc, Lc, Lc, Dc, LD, LD, LD, LD,
        nullptr, nullptr, nullptr, nullptr, 0);
    // ---- r2c = o2^T @ r1m ----
    gemm_tf32<<<gridBat, blk, GSMEM>>>(o2T, o2T, r1mT, c2,
        Lc, Dc, Lc, Lc, Lc, Lc, Lc, Dc, LD, LD, LD, LD,
        nullptr, nullptr, nullptr, nullptr, 0);

    // ---- Compare r1: [r1m | c1] @ Wc1T (K=1024), then @ Wc2T ----
    gemm_tf32<<<gridMlp, blk, GSMEM>>>(r1m, c1, Wc1T, h,
        Bc*Lc, Dc, 2*Dc, Dc, Dc, Dc, 2*Dc, Dc, 0, 0, 0, 0,
        bc1, nullptr, nullptr, nullptr, 1);
    gemm_tf32<<<gridMlp, blk, GSMEM>>>(h, h, Wc2T, out,
        Bc*Lc, Dc, Dc, Dc, Dc, Dc, Dc, Dc, 0, 0, 0, 0,
        bc2, mask1, nullptr, nullptr, 1);

    // ---- Compare r2 ----
    gemm_tf32<<<gridMlp, blk, GSMEM>>>(r2m, c2, Wc1T, h,
        Bc*Lc, Dc, 2*Dc, Dc, Dc, Dc, 2*Dc, Dc, 0, 0, 0, 0,
        bc1, nullptr, nullptr, nullptr, 1);
    gemm_tf32<<<gridMlp, blk, GSMEM>>>(h, h, Wc2T, out + (long)BLD,
        Bc*Lc, Dc, Dc, Dc, Dc, Dc, Dc, Dc, 0, 0, 0, 0,
        bc2, mask2, nullptr, nullptr, 1);
}

// round 8
// speedup vs baseline: 2.0499x; 2.0499x over previous
#include <cuda_runtime.h>
#include <cuda_fp16.h>
#include <cstdint>

// InterAttention (ESIM-style) on GB300 — fp16 mma.sync (m16n8k16, f32 accum).
// Geometry reverted to the proven R5 config: 128x128 CTA tile, 64x32 warp tile,
// 2 CTAs/SM. fp16 operands halve LDS+MMA counts per FLOP vs tf32 at identical
// mantissa precision (10 bits, round-to-nearest).
//   r1m = lrelu(lrelu(r1@W1+b1)@W2+b2)*m1
//   S   = r1m @ r2m^T + (-1e10 where !(m1&m2))
//   o1  = softmax_rows(S)*mpos ; o2 = softmax_cols(S)*mpos
//   r1c = o1 @ r2m ; r2c = o2^T @ r1m
//   out = lrelu(lrelu([xm|xc]@Wc1+bc1)@Wc2+bc2)*mask

#define NEG_INF_F (-1e10f)
#define SLOPE 0.01f
#define Bc 64
#define Lc 512
#define Dc 512
#define BLD (Bc*Lc*Dc)

// ---- scratch (static device memory) ----
__device__ float g_h[BLD];
__device__ float g_r1m[BLD];
__device__ float g_r2m[BLD];
__device__ float g_r1mT[BLD];
__device__ float g_r2mT[BLD];
__device__ float g_S[BLD];
__device__ float g_o1[BLD];
__device__ float g_o2T[BLD];
__device__ float g_c1[BLD];
__device__ float g_c2[BLD];
__device__ float g_W1T[Dc*Dc];
__device__ float g_W2T[Dc*Dc];
__device__ float g_Wc1T[2*Dc*Dc];
__device__ float g_Wc2T[Dc*Dc];

__device__ __forceinline__ void mma_f16(float* c, const uint32_t* a, const uint32_t* b) {
    asm volatile(
        "mma.sync.aligned.m16n8k16.row.col.f32.f16.f16.f32 "
        "{%0,%1,%2,%3}, {%4,%5,%6,%7}, {%8,%9}, {%0,%1,%2,%3};"
        : "+f"(c[0]), "+f"(c[1]), "+f"(c[2]), "+f"(c[3])
        : "r"(a[0]), "r"(a[1]), "r"(a[2]), "r"(a[3]), "r"(b[0]), "r"(b[1]));
}

// ---------------- fp16 GEMM ----------------
// C[b][m][n] = epilogue( sum_k opA[b][m][k] * opB[b][n][k] )
// A: [M][K] row-major f32 (K contiguous), optional concat with A2 at Ksplit.
// B: [N][K] row-major f32.
// mode 0: plain; 1: +bias, lrelu, *rowmask; 2: additive -inf mask from m1/m2.
#define BM 128
#define BN 128
#define BKH 32           // K elements per tile
#define SWH 40           // padded halves per SMEM row (80B stride, conflict-free frags)

__global__ __launch_bounds__(256, 2)
void gemm_f16(const float* __restrict__ A, const float* __restrict__ A2,
              const float* __restrict__ B, float* __restrict__ C,
              int M, int N, int K, int Ksplit,
              int ldA, int ldA2, int ldB, int ldC,
              long sA, long sA2, long sB, long sC,
              const float* __restrict__ bias,
              const int* __restrict__ rowmask,
              const int* __restrict__ m1p, const int* __restrict__ m2p,
              int mode)
{
    __shared__ __align__(16) __half As[2][BM][SWH];   // 20480 B
    __shared__ __align__(16) __half Bs[2][BN][SWH];   // 20480 B

    const int b = blockIdx.z;
    const float* Ab  = A  + (long)b * sA;
    const float* A2b = A2 + (long)b * sA2;
    const float* Bb  = B  + (long)b * sB;
    float*       Cb  = C  + (long)b * sC;

    const int tid = threadIdx.x;
    const int mBlock = blockIdx.y * BM;
    const int nBlock = blockIdx.x * BN;

    // tile-load mapping: 8 threads/row (4 f32 each), 32 rows per pass, 4 passes
    const int lrow = tid >> 3;          // 0..31
    const int lc   = (tid & 7) * 4;     // f32 col 0,4,...,28

    // warp mapping: 8 warps 2(m) x 4(n); warp tile 64x32
    const int warp = tid >> 5, lane = tid & 31;
    const int mw = (warp >> 2) * 64;
    const int nw = (warp & 3) * 32;
    const int gr = lane >> 2;     // 0..7
    const int tg = lane & 3;      // 0..3

    float acc[4][4][4];
#pragma unroll
    for (int i = 0; i < 4; i++)
#pragma unroll
        for (int j = 0; j < 4; j++)
#pragma unroll
            for (int q = 0; q < 4; q++) acc[i][j][q] = 0.0f;

    const int KT = K / BKH;
    __half2 hA[4][2], hB[4][2];   // staged (converted) tiles

    auto do_ldg = [&](int k0) {
        const float* Ap; int kb, ld;
        if (k0 < Ksplit) { Ap = Ab;  kb = k0;          ld = ldA;  }
        else             { Ap = A2b; kb = k0 - Ksplit; ld = ldA2; }
#pragma unroll
        for (int p = 0; p < 4; p++) {
            const int r = lrow + p * 32;
            float4 va = *(const float4*)(Ap + (long)(mBlock + r) * ld  + kb + lc);
            float4 vb = *(const float4*)(Bb + (long)(nBlock + r) * ldB + k0 + lc);
            hA[p][0] = __floats2half2_rn(va.x, va.y);
            hA[p][1] = __floats2half2_rn(va.z, va.w);
            hB[p][0] = __floats2half2_rn(vb.x, vb.y);
            hB[p][1] = __floats2half2_rn(vb.z, vb.w);
        }
    };
    auto do_sts = [&](int s) {
#pragma unroll
        for (int p = 0; p < 4; p++) {
            const int r = lrow + p * 32;
            *(__half2*)&As[s][r][lc]     = hA[p][0];
            *(__half2*)&As[s][r][lc + 2] = hA[p][1];
            *(__half2*)&Bs[s][r][lc]     = hB[p][0];
            *(__half2*)&Bs[s][r][lc + 2] = hB[p][1];
        }
    };

    do_ldg(0);
    do_sts(0);
    __syncthreads();

    for (int kt = 0; kt < KT; kt++) {
        const int buf = kt & 1;
        if (kt + 1 < KT) do_ldg((kt + 1) * BKH);

#pragma unroll
        for (int ks = 0; ks < 2; ks++) {        // two k16 slices
            const int kb = ks * 16;
            uint32_t af[4][4], bf[4][2];
#pragma unroll
            for (int mt = 0; mt < 4; mt++) {
                const int mr = mw + mt * 16;
                af[mt][0] = *(const uint32_t*)&As[buf][mr + gr    ][kb + tg * 2];
                af[mt][1] = *(const uint32_t*)&As[buf][mr + gr + 8][kb + tg * 2];
                af[mt][2] = *(const uint32_t*)&As[buf][mr + gr    ][kb + tg * 2 + 8];
                af[mt][3] = *(const uint32_t*)&As[buf][mr + gr + 8][kb + tg * 2 + 8];
            }
#pragma unroll
            for (int nt = 0; nt < 4; nt++) {
                const int nr = nw + nt * 8 + gr;
                bf[nt][0] = *(const uint32_t*)&Bs[buf][nr][kb + tg * 2];
                bf[nt][1] = *(const uint32_t*)&Bs[buf][nr][kb + tg * 2 + 8];
            }
#pragma unroll
            for (int mt = 0; mt < 4; mt++)
#pragma unroll
                for (int nt = 0; nt < 4; nt++)
                    mma_f16(acc[mt][nt], af[mt], bf[nt]);
        }

        if (kt + 1 < KT) do_sts((kt + 1) & 1);
        __syncthreads();
    }

    // ---- epilogue ----
#pragma unroll
    for (int mt = 0; mt < 4; mt++) {
        const int r0 = mBlock + mw + mt * 16 + gr;
#pragma unroll
        for (int half = 0; half < 2; half++) {
            const int row = r0 + half * 8;
            float rm = 1.0f; int mi = 1;
            if (mode == 1 && rowmask) rm = rowmask[(long)b * M + row] ? 1.0f : 0.0f;
            if (mode == 2) mi = m1p[(long)b * M + row];
#pragma unroll
            for (int nt = 0; nt < 4; nt++) {
                const int c0 = nBlock + nw + nt * 8 + tg * 2;
                float v0 = acc[mt][nt][half * 2 + 0];
                float v1 = acc[mt][nt][half * 2 + 1];
                if (mode == 1) {
                    v0 += bias[c0];     v1 += bias[c0 + 1];
                    v0 = (v0 >= 0.0f) ? v0 : SLOPE * v0;
                    v1 = (v1 >= 0.0f) ? v1 : SLOPE * v1;
                    v0 *= rm; v1 *= rm;
                } else if (mode == 2) {
                    const int mj0 = m2p[(long)b * N + c0];
                    const int mj1 = m2p[(long)b * N + c0 + 1];
                    v0 += (mi && mj0) ? 0.0f : NEG_INF_F;
                    v1 += (mi && mj1) ? 0.0f : NEG_INF_F;
                }
                float2 o; o.x = v0; o.y = v1;
                *(float2*)&Cb[(long)row * ldC + c0] = o;
            }
        }
    }
}

// ---------------- batched transpose ----------------
__global__ __launch_bounds__(256)
void transpose_kernel(const float* __restrict__ src, float* __restrict__ dst,
                      int rows, int cols, long sS, long sD)
{
    __shared__ float t[32][33];
    const float* s = src + (long)blockIdx.z * sS;
    float* d       = dst + (long)blockIdx.z * sD;
    const int x0 = blockIdx.x * 32;
    const int y0 = blockIdx.y * 32;
    const int tx = threadIdx.x, ty = threadIdx.y;
#pragma unroll
    for (int j = ty; j < 32; j += 8)
        t[j][tx] = s[(long)(y0 + j) * cols + x0 + tx];
    __syncthreads();
#pragma unroll
    for (int j = ty; j < 32; j += 8)
        d[(long)(x0 + j) * rows + y0 + tx] = t[tx][j];
}

// ---------------- Row softmax ----------------
__global__ __launch_bounds__(256)
void softmax_row_kernel(const float* __restrict__ S, float* __restrict__ O,
                        const int* __restrict__ m1, const int* __restrict__ m2)
{
    const int b = blockIdx.y, i = blockIdx.x;
    const float* row = S + ((long)b * Lc + i) * Lc;
    float* orow      = O + ((long)b * Lc + i) * Lc;
    const int tid = threadIdx.x;

    float v0 = row[tid], v1 = row[tid + 256];
    __shared__ float red[256];

    red[tid] = fmaxf(v0, v1);
    __syncthreads();
    for (int s = 128; s > 0; s >>= 1) {
        if (tid < s) red[tid] = fmaxf(red[tid], red[tid + s]);
        __syncthreads();
    }
    float mx = red[0];
    __syncthreads();

    float e0 = __expf(v0 - mx), e1 = __expf(v1 - mx);
    red[tid] = e0 + e1;
    __syncthreads();
    for (int s = 128; s > 0; s >>= 1) {
        if (tid < s) red[tid] += red[tid + s];
        __syncthreads();
    }
    float inv = 1.0f / red[0];

    int mi = m1[b * Lc + i];
    float f0 = (mi && m2[b * Lc + tid])       ? 1.0f : 0.0f;
    float f1 = (mi && m2[b * Lc + tid + 256]) ? 1.0f : 0.0f;
    orow[tid]       = e0 * inv * f0;
    orow[tid + 256] = e1 * inv * f1;
}

// -------- Column softmax, writes TRANSPOSED result --------
__global__ __launch_bounds__(1024)
void softmax_col_kernel(const float* __restrict__ S, float* __restrict__ OT,
                        const int* __restrict__ m1, const int* __restrict__ m2)
{
    const int b  = blockIdx.y;
    const int tx = threadIdx.x, ty = threadIdx.y;   // 32x32
    const int j  = blockIdx.x * 32 + tx;
    const float* Sb = S  + (long)b * Lc * Lc;
    float* OTb      = OT + (long)b * Lc * Lc;

    float vals[16];
    float lmax = -1e30f;
#pragma unroll
    for (int it = 0; it < 16; it++) {
        int i = ty + it * 32;
        vals[it] = Sb[(long)i * Lc + j];
        lmax = fmaxf(lmax, vals[it]);
    }
    __shared__ float red[32][33];
    red[ty][tx] = lmax;
    __syncthreads();
    for (int s = 16; s > 0; s >>= 1) {
        if (ty < s) red[ty][tx] = fmaxf(red[ty][tx], red[ty + s][tx]);
        __syncthreads();
    }
    float mx = red[0][tx];
    __syncthreads();

    float lsum = 0.0f;
#pragma unroll
    for (int it = 0; it < 16; it++) {
        vals[it] = __expf(vals[it] - mx);
        lsum += vals[it];
    }
    red[ty][tx] = lsum;
    __syncthreads();
    for (int s = 16; s > 0; s >>= 1) {
        if (ty < s) red[ty][tx] += red[ty + s][tx];
        __syncthreads();
    }
    float inv = 1.0f / red[0][tx];
    __syncthreads();

    const int mj = m2[b * Lc + j];
    const int j0 = blockIdx.x * 32;
#pragma unroll
    for (int it = 0; it < 16; it++) {
        int i = ty + it * 32;
        float f = (mj && m1[b * Lc + i]) ? 1.0f : 0.0f;
        float v = vals[it] * inv * f;
        red[ty][tx] = v;
        __syncthreads();
        OTb[(long)(j0 + ty) * Lc + it * 32 + tx] = red[tx][ty];
        __syncthreads();
    }
}

// ---------------- Launch ----------------
extern "C" void kernel_launch(void* const* d_in, const int* in_sizes, int n_in,
                              void* d_out, int out_size)
{
    const float* r1    = (const float*)d_in[0];
    const float* r2    = (const float*)d_in[1];
    const int*   mask1 = (const int*)  d_in[2];
    const int*   mask2 = (const int*)  d_in[3];
    const float* W1    = (const float*)d_in[4];
    const float* b1    = (const float*)d_in[5];
    const float* W2    = (const float*)d_in[6];
    const float* b2    = (const float*)d_in[7];
    const float* Wc1   = (const float*)d_in[8];   // [1024, 512]
    const float* bc1   = (const float*)d_in[9];
    const float* Wc2   = (const float*)d_in[10];
    const float* bc2   = (const float*)d_in[11];
    float* out = (float*)d_out;

    float *h, *r1m, *r2m, *r1mT, *r2mT, *S, *o1, *o2T, *c1, *c2;
    float *W1T, *W2T, *Wc1T, *Wc2T;
    cudaGetSymbolAddress((void**)&h,    g_h);
    cudaGetSymbolAddress((void**)&r1m,  g_r1m);
    cudaGetSymbolAddress((void**)&r2m,  g_r2m);
    cudaGetSymbolAddress((void**)&r1mT, g_r1mT);
    cudaGetSymbolAddress((void**)&r2mT, g_r2mT);
    cudaGetSymbolAddress((void**)&S,    g_S);
    cudaGetSymbolAddress((void**)&o1,   g_o1);
    cudaGetSymbolAddress((void**)&o2T,  g_o2T);
    cudaGetSymbolAddress((void**)&c1,   g_c1);
    cudaGetSymbolAddress((void**)&c2,   g_c2);
    cudaGetSymbolAddress((void**)&W1T,  g_W1T);
    cudaGetSymbolAddress((void**)&W2T,  g_W2T);
    cudaGetSymbolAddress((void**)&Wc1T, g_Wc1T);
    cudaGetSymbolAddress((void**)&Wc2T, g_Wc2T);

    const long LD = (long)Lc * Dc;   // 262144
    dim3 blk(256);
    dim3 gridMlp(Dc / BN, (Bc * Lc) / BM, 1);   // (4, 256, 1)
    dim3 gridBat(Dc / BN, Lc / BM, Bc);         // (4, 4, 64)
    dim3 tblk(32, 8);

    // ---- transpose weights (K-contiguous B operands) ----
    transpose_kernel<<<dim3(Dc/32, Dc/32, 1), tblk>>>(W1,  W1T,  Dc,   Dc, 0, 0);
    transpose_kernel<<<dim3(Dc/32, Dc/32, 1), tblk>>>(W2,  W2T,  Dc,   Dc, 0, 0);
    transpose_kernel<<<dim3(Dc/32, 2*Dc/32, 1), tblk>>>(Wc1, Wc1T, 2*Dc, Dc, 0, 0);
    transpose_kernel<<<dim3(Dc/32, Dc/32, 1), tblk>>>(Wc2, Wc2T, Dc,   Dc, 0, 0);

    // ---- MLP r1 ----
    gemm_f16<<<gridMlp, blk>>>(r1, r1, W1T, h,
        Bc*Lc, Dc, Dc, Dc, Dc, Dc, Dc, Dc, 0, 0, 0, 0,
        b1, nullptr, nullptr, nullptr, 1);
    gemm_f16<<<gridMlp, blk>>>(h, h, W2T, r1m,
        Bc*Lc, Dc, Dc, Dc, Dc, Dc, Dc, Dc, 0, 0, 0, 0,
        b2, mask1, nullptr, nullptr, 1);
    // ---- MLP r2 ----
    gemm_f16<<<gridMlp, blk>>>(r2, r2, W1T, h,
        Bc*Lc, Dc, Dc, Dc, Dc, Dc, Dc, Dc, 0, 0, 0, 0,
        b1, nullptr, nullptr, nullptr, 1);
    gemm_f16<<<gridMlp, blk>>>(h, h, W2T, r2m,
        Bc*Lc, Dc, Dc, Dc, Dc, Dc, Dc, Dc, 0, 0, 0, 0,
        b2, mask2, nullptr, nullptr, 1);

    // ---- Scores: S = r1m @ r2m^T + mask ----
    gemm_f16<<<dim3(Lc/BN, Lc/BM, Bc), blk>>>(r1m, r1m, r2m, S,
        Lc, Lc, Dc, Dc, Dc, Dc, Dc, Lc, LD, LD, LD, LD,
        nullptr, nullptr, mask1, mask2, 2);

    // ---- Softmaxes (col writes o2^T; row writes o1) ----
    softmax_col_kernel<<<dim3(Lc/32, Bc), dim3(32, 32)>>>(S, o2T, mask1, mask2);
    softmax_row_kernel<<<dim3(Lc, Bc), 256>>>(S, o1, mask1, mask2);

    // ---- transpose activations for value GEMMs ----
    transpose_kernel<<<dim3(Dc/32, Lc/32, Bc), tblk>>>(r1m, r1mT, Lc, Dc, LD, LD);
    transpose_kernel<<<dim3(Dc/32, Lc/32, Bc), tblk>>>(r2m, r2mT, Lc, Dc, LD, LD);

    // ---- r1c = o1 @ r2m ----
    gemm_f16<<<gridBat, blk>>>(o1, o1, r2mT, c1,
        Lc, Dc, Lc, Lc, Lc, Lc, Lc, Dc, LD, LD, LD, LD,
        nullptr, nullptr, nullptr, nullptr, 0);
    // ---- r2c = o2^T @ r1m ----
    gemm_f16<<<gridBat, blk>>>(o2T, o2T, r1mT, c2,
        Lc, Dc, Lc, Lc, Lc, Lc, Lc, Dc, LD, LD, LD, LD,
        nullptr, nullptr, nullptr, nullptr, 0);

    // ---- Compare r1: [r1m | c1] @ Wc1T (K=1024), then @ Wc2T ----
    gemm_f16<<<gridMlp, blk>>>(r1m, c1, Wc1T, h,
        Bc*Lc, Dc, 2*Dc, Dc, Dc, Dc, 2*Dc, Dc, 0, 0, 0, 0,
        bc1, nullptr, nullptr, nullptr, 1);
    gemm_f16<<<gridMlp, blk>>>(h, h, Wc2T, out,
        Bc*Lc, Dc, Dc, Dc, Dc, Dc, Dc, Dc, 0, 0, 0, 0,
        bc2, mask1, nullptr, nullptr, 1);

    // ---- Compare r2 ----
    gemm_f16<<<gridMlp, blk>>>(r2m, c2, Wc1T, h,
        Bc*Lc, Dc, 2*Dc, Dc, Dc, Dc, 2*Dc, Dc, 0, 0, 0, 0,
        bc1, nullptr, nullptr, nullptr, 1);
    gemm_f16<<<gridMlp, blk>>>(h, h, Wc2T, out + (long)BLD,
        Bc*Lc, Dc, Dc, Dc, Dc, Dc, Dc, Dc, 0, 0, 0, 0,
        bc2, mask2, nullptr, nullptr, 1);
}

// round 9
// speedup vs baseline: 2.3549x; 1.1488x over previous
#include <cuda_runtime.h>
#include <cuda_fp16.h>
#include <cstdint>

// InterAttention (ESIM-style) on GB300 — fp16 mma.sync with fp16 intermediates.
// All GEMM operands live in fp16 (identical rounding points as before: values
// were already rn-rounded to fp16 at GEMM load). Only S (softmax logits) and
// the final outputs stay f32.
//   r1m = lrelu(lrelu(r1@W1+b1)@W2+b2)*m1
//   S   = r1m @ r2m^T + (-1e10 where !(m1&m2))
//   o1  = softmax_rows(S)*mpos ; o2 = softmax_cols(S)*mpos
//   r1c = o1 @ r2m ; r2c = o2^T @ r1m
//   out = lrelu(lrelu([xm|xc]@Wc1+bc1)@Wc2+bc2)*mask

#define NEG_INF_F (-1e10f)
#define SLOPE 0.01f
#define Bc 64
#define Lc 512
#define Dc 512
#define BLD (Bc*Lc*Dc)

// ---- scratch (static device memory) ----
__device__ __half g_r1h[BLD];
__device__ __half g_r2h[BLD];
__device__ __half g_hh[BLD];
__device__ __half g_r1mh[BLD];
__device__ __half g_r2mh[BLD];
__device__ __half g_r1mTh[BLD];
__device__ __half g_r2mTh[BLD];
__device__ __half g_o1h[BLD];
__device__ __half g_o2Th[BLD];
__device__ __half g_c1h[BLD];
__device__ __half g_c2h[BLD];
__device__ __half g_W1Th[Dc*Dc];
__device__ __half g_W2Th[Dc*Dc];
__device__ __half g_Wc1Th[2*Dc*Dc];
__device__ __half g_Wc2Th[Dc*Dc];
__device__ float  g_S[BLD];

__device__ __forceinline__ void mma_f16(float* c, const uint32_t* a, const uint32_t* b) {
    asm volatile(
        "mma.sync.aligned.m16n8k16.row.col.f32.f16.f16.f32 "
        "{%0,%1,%2,%3}, {%4,%5,%6,%7}, {%8,%9}, {%0,%1,%2,%3};"
        : "+f"(c[0]), "+f"(c[1]), "+f"(c[2]), "+f"(c[3])
        : "r"(a[0]), "r"(a[1]), "r"(a[2]), "r"(a[3]), "r"(b[0]), "r"(b[1]));
}

// ---------------- fp16 GEMM (half in, half/float out) ----------------
// C[b][m][n] = epilogue( sum_k opA[b][m][k] * opB[b][n][k] )
// A: [M][K] half row-major (K contiguous), optional concat with A2 at Ksplit
//    (pass A2=A, Ksplit=0 for no concat). B: [N][K] half.
// mode 0: plain; 1: +bias, lrelu, *rowmask; 2: additive -inf mask (float out).
// outHalf: 1 -> C is __half*, 0 -> C is float*.
#define BM 128
#define BN 128
#define BKH 32           // K halves per tile
#define SWH 40           // padded halves per SMEM row (80B stride)

__global__ __launch_bounds__(256, 2)
void gemm_h(const __half* __restrict__ A, const __half* __restrict__ A2,
            const __half* __restrict__ B, void* __restrict__ Cv,
            int M, int N, int K, int Ksplit,
            int ldA, int ldA2, int ldB, int ldC,
            long sA, long sA2, long sB, long sC,
            const float* __restrict__ bias,
            const int* __restrict__ rowmask,
            const int* __restrict__ m1p, const int* __restrict__ m2p,
            int mode, int outHalf)
{
    __shared__ __align__(16) __half As[2][BM][SWH];   // 20480 B
    __shared__ __align__(16) __half Bs[2][BN][SWH];   // 20480 B

    const int b = blockIdx.z;
    const __half* Ab  = A  + (long)b * sA;
    const __half* A2b = A2 + (long)b * sA2;
    const __half* Bb  = B  + (long)b * sB;

    const int tid = threadIdx.x;
    const int mBlock = blockIdx.y * BM;
    const int nBlock = blockIdx.x * BN;

    // tile-load mapping: 4 threads/row (8 halves = 16B each), 64 rows/pass, 2 passes
    const int lrow = tid >> 2;          // 0..63
    const int lc8  = (tid & 3) * 8;     // half col 0,8,16,24

    // warp mapping: 8 warps 2(m) x 4(n); warp tile 64x32
    const int warp = tid >> 5, lane = tid & 31;
    const int mw = (warp >> 2) * 64;
    const int nw = (warp & 3) * 32;
    const int gr = lane >> 2;     // 0..7
    const int tg = lane & 3;      // 0..3

    float acc[4][4][4];
#pragma unroll
    for (int i = 0; i < 4; i++)
#pragma unroll
        for (int j = 0; j < 4; j++)
#pragma unroll
            for (int q = 0; q < 4; q++) acc[i][j][q] = 0.0f;

    const int KT = K / BKH;
    uint4 sa[2], sb[2];

    auto do_ldg = [&](int k0) {
        const __half* Ap; int kb, ld;
        if (k0 < Ksplit) { Ap = Ab;  kb = k0;          ld = ldA;  }
        else             { Ap = A2b; kb = k0 - Ksplit; ld = ldA2; }
#pragma unroll
        for (int p = 0; p < 2; p++) {
            const int r = lrow + p * 64;
            sa[p] = *(const uint4*)(Ap + (long)(mBlock + r) * ld  + kb + lc8);
            sb[p] = *(const uint4*)(Bb + (long)(nBlock + r) * ldB + k0 + lc8);
        }
    };
    auto do_sts = [&](int s) {
#pragma unroll
        for (int p = 0; p < 2; p++) {
            const int r = lrow + p * 64;
            *(uint4*)&As[s][r][lc8] = sa[p];
            *(uint4*)&Bs[s][r][lc8] = sb[p];
        }
    };

    do_ldg(0);
    do_sts(0);
    __syncthreads();

    for (int kt = 0; kt < KT; kt++) {
        const int buf = kt & 1;
        if (kt + 1 < KT) do_ldg((kt + 1) * BKH);

#pragma unroll
        for (int ks = 0; ks < 2; ks++) {        // two k16 slices
            const int kb = ks * 16;
            uint32_t af[4][4], bf[4][2];
#pragma unroll
            for (int mt = 0; mt < 4; mt++) {
                const int mr = mw + mt * 16;
                af[mt][0] = *(const uint32_t*)&As[buf][mr + gr    ][kb + tg * 2];
                af[mt][1] = *(const uint32_t*)&As[buf][mr + gr + 8][kb + tg * 2];
                af[mt][2] = *(const uint32_t*)&As[buf][mr + gr    ][kb + tg * 2 + 8];
                af[mt][3] = *(const uint32_t*)&As[buf][mr + gr + 8][kb + tg * 2 + 8];
            }
#pragma unroll
            for (int nt = 0; nt < 4; nt++) {
                const int nr = nw + nt * 8 + gr;
                bf[nt][0] = *(const uint32_t*)&Bs[buf][nr][kb + tg * 2];
                bf[nt][1] = *(const uint32_t*)&Bs[buf][nr][kb + tg * 2 + 8];
            }
#pragma unroll
            for (int mt = 0; mt < 4; mt++)
#pragma unroll
                for (int nt = 0; nt < 4; nt++)
                    mma_f16(acc[mt][nt], af[mt], bf[nt]);
        }

        if (kt + 1 < KT) do_sts((kt + 1) & 1);
        __syncthreads();
    }

    // ---- epilogue ----
    float*  Cf = (float*) Cv + (long)b * sC;
    __half* Ch = (__half*)Cv + (long)b * sC;
#pragma unroll
    for (int mt = 0; mt < 4; mt++) {
        const int r0 = mBlock + mw + mt * 16 + gr;
#pragma unroll
        for (int half_ = 0; half_ < 2; half_++) {
            const int row = r0 + half_ * 8;
            float rm = 1.0f; int mi = 1;
            if (mode == 1 && rowmask) rm = rowmask[(long)b * M + row] ? 1.0f : 0.0f;
            if (mode == 2) mi = m1p[(long)b * M + row];
#pragma unroll
            for (int nt = 0; nt < 4; nt++) {
                const int c0 = nBlock + nw + nt * 8 + tg * 2;
                float v0 = acc[mt][nt][half_ * 2 + 0];
                float v1 = acc[mt][nt][half_ * 2 + 1];
                if (mode == 1) {
                    v0 += bias[c0];     v1 += bias[c0 + 1];
                    v0 = (v0 >= 0.0f) ? v0 : SLOPE * v0;
                    v1 = (v1 >= 0.0f) ? v1 : SLOPE * v1;
                    v0 *= rm; v1 *= rm;
                } else if (mode == 2) {
                    const int mj0 = m2p[(long)b * N + c0];
                    const int mj1 = m2p[(long)b * N + c0 + 1];
                    v0 += (mi && mj0) ? 0.0f : NEG_INF_F;
                    v1 += (mi && mj1) ? 0.0f : NEG_INF_F;
                }
                if (outHalf) {
                    *(__half2*)&Ch[(long)row * ldC + c0] = __floats2half2_rn(v0, v1);
                } else {
                    float2 o; o.x = v0; o.y = v1;
                    *(float2*)&Cf[(long)row * ldC + c0] = o;
                }
            }
        }
    }
}

// ---------------- f32 -> f16 elementwise convert ----------------
__global__ __launch_bounds__(256)
void f2h_kernel(const float* __restrict__ src, __half* __restrict__ dst, int n)
{
    int i = (blockIdx.x * 256 + threadIdx.x) * 4;
    if (i < n) {
        float4 v = *(const float4*)(src + i);
        *(__half2*)(dst + i)     = __floats2half2_rn(v.x, v.y);
        *(__half2*)(dst + i + 2) = __floats2half2_rn(v.z, v.w);
    }
}

// ---------------- transpose f32 -> f16 (weights) ----------------
__global__ __launch_bounds__(256)
void transpose_f2h(const float* __restrict__ src, __half* __restrict__ dst,
                   int rows, int cols)
{
    __shared__ float t[32][33];
    const int x0 = blockIdx.x * 32;
    const int y0 = blockIdx.y * 32;
    const int tx = threadIdx.x, ty = threadIdx.y;
#pragma unroll
    for (int j = ty; j < 32; j += 8)
        t[j][tx] = src[(long)(y0 + j) * cols + x0 + tx];
    __syncthreads();
#pragma unroll
    for (int j = ty; j < 32; j += 8)
        dst[(long)(x0 + j) * rows + y0 + tx] = __float2half_rn(t[tx][j]);
}

// ---------------- batched transpose half -> half ----------------
__global__ __launch_bounds__(256)
void transpose_h(const __half* __restrict__ src, __half* __restrict__ dst,
                 int rows, int cols, long sS, long sD)
{
    __shared__ __half t[32][34];
    const __half* s = src + (long)blockIdx.z * sS;
    __half* d       = dst + (long)blockIdx.z * sD;
    const int x0 = blockIdx.x * 32;
    const int y0 = blockIdx.y * 32;
    const int tx = threadIdx.x, ty = threadIdx.y;
#pragma unroll
    for (int j = ty; j < 32; j += 8)
        t[j][tx] = s[(long)(y0 + j) * cols + x0 + tx];
    __syncthreads();
#pragma unroll
    for (int j = ty; j < 32; j += 8)
        d[(long)(x0 + j) * rows + y0 + tx] = t[tx][j];
}

// ---------------- Row softmax: o1 (half) = softmax_rows(S)*mpos ----------------
__global__ __launch_bounds__(256)
void softmax_row_kernel(const float* __restrict__ S, __half* __restrict__ O,
                        const int* __restrict__ m1, const int* __restrict__ m2)
{
    const int b = blockIdx.y, i = blockIdx.x;
    const float* row = S + ((long)b * Lc + i) * Lc;
    __half* orow     = O + ((long)b * Lc + i) * Lc;
    const int tid = threadIdx.x;

    float v0 = row[tid], v1 = row[tid + 256];
    __shared__ float red[256];

    red[tid] = fmaxf(v0, v1);
    __syncthreads();
    for (int s = 128; s > 0; s >>= 1) {
        if (tid < s) red[tid] = fmaxf(red[tid], red[tid + s]);
        __syncthreads();
    }
    float mx = red[0];
    __syncthreads();

    float e0 = __expf(v0 - mx), e1 = __expf(v1 - mx);
    red[tid] = e0 + e1;
    __syncthreads();
    for (int s = 128; s > 0; s >>= 1) {
        if (tid < s) red[tid] += red[tid + s];
        __syncthreads();
    }
    float inv = 1.0f / red[0];

    int mi = m1[b * Lc + i];
    float f0 = (mi && m2[b * Lc + tid])       ? 1.0f : 0.0f;
    float f1 = (mi && m2[b * Lc + tid + 256]) ? 1.0f : 0.0f;
    orow[tid]       = __float2half_rn(e0 * inv * f0);
    orow[tid + 256] = __float2half_rn(e1 * inv * f1);
}

// -------- Column softmax, writes TRANSPOSED half result --------
__global__ __launch_bounds__(1024)
void softmax_col_kernel(const float* __restrict__ S, __half* __restrict__ OT,
                        const int* __restrict__ m1, const int* __restrict__ m2)
{
    const int b  = blockIdx.y;
    const int tx = threadIdx.x, ty = threadIdx.y;   // 32x32
    const int j  = blockIdx.x * 32 + tx;
    const float* Sb = S  + (long)b * Lc * Lc;
    __half* OTb     = OT + (long)b * Lc * Lc;

    float vals[16];
    float lmax = -1e30f;
#pragma unroll
    for (int it = 0; it < 16; it++) {
        int i = ty + it * 32;
        vals[it] = Sb[(long)i * Lc + j];
        lmax = fmaxf(lmax, vals[it]);
    }
    __shared__ float red[32][33];
    red[ty][tx] = lmax;
    __syncthreads();
    for (int s = 16; s > 0; s >>= 1) {
        if (ty < s) red[ty][tx] = fmaxf(red[ty][tx], red[ty + s][tx]);
        __syncthreads();
    }
    float mx = red[0][tx];
    __syncthreads();

    float lsum = 0.0f;
#pragma unroll
    for (int it = 0; it < 16; it++) {
        vals[it] = __expf(vals[it] - mx);
        lsum += vals[it];
    }
    red[ty][tx] = lsum;
    __syncthreads();
    for (int s = 16; s > 0; s >>= 1) {
        if (ty < s) red[ty][tx] += red[ty + s][tx];
        __syncthreads();
    }
    float inv = 1.0f / red[0][tx];
    __syncthreads();

    const int mj = m2[b * Lc + j];
    const int j0 = blockIdx.x * 32;
#pragma unroll
    for (int it = 0; it < 16; it++) {
        int i = ty + it * 32;
        float f = (mj && m1[b * Lc + i]) ? 1.0f : 0.0f;
        float v = vals[it] * inv * f;
        red[ty][tx] = v;
        __syncthreads();
        OTb[(long)(j0 + ty) * Lc + it * 32 + tx] = __float2half_rn(red[tx][ty]);
        __syncthreads();
    }
}

// ---------------- Launch ----------------
extern "C" void kernel_launch(void* const* d_in, const int* in_sizes, int n_in,
                              void* d_out, int out_size)
{
    const float* r1    = (const float*)d_in[0];
    const float* r2    = (const float*)d_in[1];
    const int*   mask1 = (const int*)  d_in[2];
    const int*   mask2 = (const int*)  d_in[3];
    const float* W1    = (const float*)d_in[4];
    const float* b1    = (const float*)d_in[5];
    const float* W2    = (const float*)d_in[6];
    const float* b2    = (const float*)d_in[7];
    const float* Wc1   = (const float*)d_in[8];   // [1024, 512]
    const float* bc1   = (const float*)d_in[9];
    const float* Wc2   = (const float*)d_in[10];
    const float* bc2   = (const float*)d_in[11];
    float* out = (float*)d_out;

    __half *r1h, *r2h, *hh, *r1mh, *r2mh, *r1mTh, *r2mTh, *o1h, *o2Th, *c1h, *c2h;
    __half *W1Th, *W2Th, *Wc1Th, *Wc2Th;
    float *S;
    cudaGetSymbolAddress((void**)&r1h,   g_r1h);
    cudaGetSymbolAddress((void**)&r2h,   g_r2h);
    cudaGetSymbolAddress((void**)&hh,    g_hh);
    cudaGetSymbolAddress((void**)&r1mh,  g_r1mh);
    cudaGetSymbolAddress((void**)&r2mh,  g_r2mh);
    cudaGetSymbolAddress((void**)&r1mTh, g_r1mTh);
    cudaGetSymbolAddress((void**)&r2mTh, g_r2mTh);
    cudaGetSymbolAddress((void**)&o1h,   g_o1h);
    cudaGetSymbolAddress((void**)&o2Th,  g_o2Th);
    cudaGetSymbolAddress((void**)&c1h,   g_c1h);
    cudaGetSymbolAddress((void**)&c2h,   g_c2h);
    cudaGetSymbolAddress((void**)&W1Th,  g_W1Th);
    cudaGetSymbolAddress((void**)&W2Th,  g_W2Th);
    cudaGetSymbolAddress((void**)&Wc1Th, g_Wc1Th);
    cudaGetSymbolAddress((void**)&Wc2Th, g_Wc2Th);
    cudaGetSymbolAddress((void**)&S,     g_S);

    const long LD = (long)Lc * Dc;   // 262144
    dim3 blk(256);
    dim3 gridMlp(Dc / BN, (Bc * Lc) / BM, 1);   // (4, 256, 1)
    dim3 gridBat(Dc / BN, Lc / BM, Bc);         // (4, 4, 64)
    dim3 tblk(32, 8);

    // ---- convert inputs to half ----
    f2h_kernel<<<BLD / 4 / 256, 256>>>(r1, r1h, BLD);
    f2h_kernel<<<BLD / 4 / 256, 256>>>(r2, r2h, BLD);

    // ---- transpose weights to half (K-contiguous B operands) ----
    transpose_f2h<<<dim3(Dc/32, Dc/32), tblk>>>(W1,  W1Th,  Dc,   Dc);
    transpose_f2h<<<dim3(Dc/32, Dc/32), tblk>>>(W2,  W2Th,  Dc,   Dc);
    transpose_f2h<<<dim3(Dc/32, 2*Dc/32), tblk>>>(Wc1, Wc1Th, 2*Dc, Dc);
    transpose_f2h<<<dim3(Dc/32, Dc/32), tblk>>>(Wc2, Wc2Th, Dc,   Dc);

    // ---- MLP r1 ----
    gemm_h<<<gridMlp, blk>>>(r1h, r1h, W1Th, hh,
        Bc*Lc, Dc, Dc, 0, Dc, Dc, Dc, Dc, 0, 0, 0, 0,
        b1, nullptr, nullptr, nullptr, 1, 1);
    gemm_h<<<gridMlp, blk>>>(hh, hh, W2Th, r1mh,
        Bc*Lc, Dc, Dc, 0, Dc, Dc, Dc, Dc, 0, 0, 0, 0,
        b2, mask1, nullptr, nullptr, 1, 1);
    // ---- MLP r2 ----
    gemm_h<<<gridMlp, blk>>>(r2h, r2h, W1Th, hh,
        Bc*Lc, Dc, Dc, 0, Dc, Dc, Dc, Dc, 0, 0, 0, 0,
        b1, nullptr, nullptr, nullptr, 1, 1);
    gemm_h<<<gridMlp, blk>>>(hh, hh, W2Th, r2mh,
        Bc*Lc, Dc, Dc, 0, Dc, Dc, Dc, Dc, 0, 0, 0, 0,
        b2, mask2, nullptr, nullptr, 1, 1);

    // ---- Scores: S (float) = r1m @ r2m^T + mask ----
    gemm_h<<<dim3(Lc/BN, Lc/BM, Bc), blk>>>(r1mh, r1mh, r2mh, S,
        Lc, Lc, Dc, 0, Dc, Dc, Dc, Lc, LD, LD, LD, LD,
        nullptr, nullptr, mask1, mask2, 2, 0);

    // ---- Softmaxes (half outputs; col writes o2^T) ----
    softmax_col_kernel<<<dim3(Lc/32, Bc), dim3(32, 32)>>>(S, o2Th, mask1, mask2);
    softmax_row_kernel<<<dim3(Lc, Bc), 256>>>(S, o1h, mask1, mask2);

    // ---- transpose activations for value GEMMs (half) ----
    transpose_h<<<dim3(Dc/32, Lc/32, Bc), tblk>>>(r1mh, r1mTh, Lc, Dc, LD, LD);
    transpose_h<<<dim3(Dc/32, Lc/32, Bc), tblk>>>(r2mh, r2mTh, Lc, Dc, LD, LD);

    // ---- r1c = o1 @ r2m ----
    gemm_h<<<gridBat, blk>>>(o1h, o1h, r2mTh, c1h,
        Lc, Dc, Lc, 0, Lc, Lc, Lc, Dc, LD, LD, LD, LD,
        nullptr, nullptr, nullptr, nullptr, 0, 1);
    // ---- r2c = o2^T @ r1m ----
    gemm_h<<<gridBat, blk>>>(o2Th, o2Th, r1mTh, c2h,
        Lc, Dc, Lc, 0, Lc, Lc, Lc, Dc, LD, LD, LD, LD,
        nullptr, nullptr, nullptr, nullptr, 0, 1);

    // ---- Compare r1: [r1m | c1] @ Wc1T (K=1024), then @ Wc2T -> out (f32) ----
    gemm_h<<<gridMlp, blk>>>(r1mh, c1h, Wc1Th, hh,
        Bc*Lc, Dc, 2*Dc, Dc, Dc, Dc, 2*Dc, Dc, 0, 0, 0, 0,
        bc1, nullptr, nullptr, nullptr, 1, 1);
    gemm_h<<<gridMlp, blk>>>(hh, hh, Wc2Th, out,
        Bc*Lc, Dc, Dc, 0, Dc, Dc, Dc, Dc, 0, 0, 0, 0,
        bc2, mask1, nullptr, nullptr, 1, 0);

    // ---- Compare r2 ----
    gemm_h<<<gridMlp, blk>>>(r2mh, c2h, Wc1Th, hh,
        Bc*Lc, Dc, 2*Dc, Dc, Dc, Dc, 2*Dc, Dc, 0, 0, 0, 0,
        bc1, nullptr, nullptr, nullptr, 1, 1);
    gemm_h<<<gridMlp, blk>>>(hh, hh, Wc2Th, out + (long)BLD,
        Bc*Lc, Dc, Dc, 0, Dc, Dc, Dc, Dc, 0, 0, 0, 0,
        bc2, mask2, nullptr, nullptr, 1, 0);
}

// round 10
// speedup vs baseline: 2.6284x; 1.1161x over previous
#include <cuda_runtime.h>
#include <cuda_fp16.h>
#include <cstdint>

// InterAttention (ESIM-style) on GB300 — fp16 mma.sync + ldmatrix fragment loads.
// fp16 intermediates end-to-end; only S (softmax logits) and final outputs f32.
//   r1m = lrelu(lrelu(r1@W1+b1)@W2+b2)*m1
//   S   = r1m @ r2m^T + (-1e10 where !(m1&m2))
//   o1  = softmax_rows(S)*mpos ; o2 = softmax_cols(S)*mpos
//   r1c = o1 @ r2m ; r2c = o2^T @ r1m
//   out = lrelu(lrelu([xm|xc]@Wc1+bc1)@Wc2+bc2)*mask

#define NEG_INF_F (-1e10f)
#define SLOPE 0.01f
#define Bc 64
#define Lc 512
#define Dc 512
#define BLD (Bc*Lc*Dc)

// ---- scratch (static device memory) ----
__device__ __half g_r1h[BLD];
__device__ __half g_r2h[BLD];
__device__ __half g_hh[BLD];
__device__ __half g_r1mh[BLD];
__device__ __half g_r2mh[BLD];
__device__ __half g_r1mTh[BLD];
__device__ __half g_r2mTh[BLD];
__device__ __half g_o1h[BLD];
__device__ __half g_o2Th[BLD];
__device__ __half g_c1h[BLD];
__device__ __half g_c2h[BLD];
__device__ __half g_W1Th[Dc*Dc];
__device__ __half g_W2Th[Dc*Dc];
__device__ __half g_Wc1Th[2*Dc*Dc];
__device__ __half g_Wc2Th[Dc*Dc];
__device__ float  g_S[BLD];

__device__ __forceinline__ void mma_f16(float* c, const uint32_t* a, const uint32_t* b) {
    asm volatile(
        "mma.sync.aligned.m16n8k16.row.col.f32.f16.f16.f32 "
        "{%0,%1,%2,%3}, {%4,%5,%6,%7}, {%8,%9}, {%0,%1,%2,%3};"
        : "+f"(c[0]), "+f"(c[1]), "+f"(c[2]), "+f"(c[3])
        : "r"(a[0]), "r"(a[1]), "r"(a[2]), "r"(a[3]), "r"(b[0]), "r"(b[1]));
}

#define LDSM_X4(r0, r1, r2, r3, addr) \
    asm volatile("ldmatrix.sync.aligned.m8n8.x4.shared.b16 {%0,%1,%2,%3}, [%4];" \
        : "=r"(r0), "=r"(r1), "=r"(r2), "=r"(r3) : "r"(addr))

__device__ __forceinline__ uint32_t smem_u32(const void* p){
    uint32_t a;
    asm("{ .reg .u64 t; cvta.to.shared.u64 t, %1; cvt.u32.u64 %0, t; }":"=r"(a):"l"(p));
    return a;
}

// ---------------- fp16 GEMM (half in, half/float out) ----------------
// C[b][m][n] = epilogue( sum_k opA[b][m][k] * opB[b][n][k] )
// A: [M][K] half row-major (K contiguous), optional concat with A2 at Ksplit
//    (pass A2=A, Ksplit=0 for no concat). B: [N][K] half.
// mode 0: plain; 1: +bias, lrelu, *rowmask; 2: additive -inf mask (float out).
// outHalf: 1 -> C is __half*, 0 -> C is float*.
#define BM 128
#define BN 128
#define BKH 32           // K halves per tile
#define SWH 40           // padded halves per SMEM row (80B = 16*5: 16B-aligned rows)

__global__ __launch_bounds__(256, 2)
void gemm_h(const __half* __restrict__ A, const __half* __restrict__ A2,
            const __half* __restrict__ B, void* __restrict__ Cv,
            int M, int N, int K, int Ksplit,
            int ldA, int ldA2, int ldB, int ldC,
            long sA, long sA2, long sB, long sC,
            const float* __restrict__ bias,
            const int* __restrict__ rowmask,
            const int* __restrict__ m1p, const int* __restrict__ m2p,
            int mode, int outHalf)
{
    __shared__ __align__(16) __half As[2][BM][SWH];   // 20480 B
    __shared__ __align__(16) __half Bs[2][BN][SWH];   // 20480 B

    const int b = blockIdx.z;
    const __half* Ab  = A  + (long)b * sA;
    const __half* A2b = A2 + (long)b * sA2;
    const __half* Bb  = B  + (long)b * sB;

    const int tid = threadIdx.x;
    const int mBlock = blockIdx.y * BM;
    const int nBlock = blockIdx.x * BN;

    // tile-load mapping: 4 threads/row (8 halves = 16B each), 64 rows/pass, 2 passes
    const int lrow = tid >> 2;          // 0..63
    const int lc8  = (tid & 3) * 8;     // half col 0,8,16,24

    // warp mapping: 8 warps 2(m) x 4(n); warp tile 64x32
    const int warp = tid >> 5, lane = tid & 31;
    const int mw = (warp >> 2) * 64;
    const int nw = (warp & 3) * 32;
    const int gr = lane >> 2;     // 0..7
    const int tg = lane & 3;      // 0..3

    // ldmatrix per-lane byte offsets (within one buffer)
    const uint32_t aBase = smem_u32(&As[0][0][0]);
    const uint32_t bBase = smem_u32(&Bs[0][0][0]);
    const uint32_t ABYTES = BM * SWH * 2;
    const uint32_t BBYTES = BN * SWH * 2;
    uint32_t aOff[4], bOff[2];
    {
        const int g = lane >> 3;            // 8-lane group 0..3
#pragma unroll
        for (int mt = 0; mt < 4; mt++)
            aOff[mt] = (uint32_t)(((mw + mt * 16 + (lane & 15)) * SWH + (lane >> 4) * 8) * 2);
#pragma unroll
        for (int p = 0; p < 2; p++)
            bOff[p] = (uint32_t)(((nw + (p * 2 + (g >> 1)) * 8 + (lane & 7)) * SWH + (g & 1) * 8) * 2);
    }

    float acc[4][4][4];
#pragma unroll
    for (int i = 0; i < 4; i++)
#pragma unroll
        for (int j = 0; j < 4; j++)
#pragma unroll
            for (int q = 0; q < 4; q++) acc[i][j][q] = 0.0f;

    const int KT = K / BKH;
    uint4 sa[2], sb[2];

    auto do_ldg = [&](int k0) {
        const __half* Ap; int kb, ld;
        if (k0 < Ksplit) { Ap = Ab;  kb = k0;          ld = ldA;  }
        else             { Ap = A2b; kb = k0 - Ksplit; ld = ldA2; }
#pragma unroll
        for (int p = 0; p < 2; p++) {
            const int r = lrow + p * 64;
            sa[p] = *(const uint4*)(Ap + (long)(mBlock + r) * ld  + kb + lc8);
            sb[p] = *(const uint4*)(Bb + (long)(nBlock + r) * ldB + k0 + lc8);
        }
    };
    auto do_sts = [&](int s) {
#pragma unroll
        for (int p = 0; p < 2; p++) {
            const int r = lrow + p * 64;
            *(uint4*)&As[s][r][lc8] = sa[p];
            *(uint4*)&Bs[s][r][lc8] = sb[p];
        }
    };

    do_ldg(0);
    do_sts(0);
    __syncthreads();

    for (int kt = 0; kt < KT; kt++) {
        const int buf = kt & 1;
        if (kt + 1 < KT) do_ldg((kt + 1) * BKH);

        const uint32_t aBuf = aBase + buf * ABYTES;
        const uint32_t bBuf = bBase + buf * BBYTES;
#pragma unroll
        for (int ks = 0; ks < 2; ks++) {        // two k16 slices
            const uint32_t kbB = ks * 32;       // 16 halves = 32 bytes
            uint32_t af[4][4], bf[4][2];
#pragma unroll
            for (int mt = 0; mt < 4; mt++)
                LDSM_X4(af[mt][0], af[mt][1], af[mt][2], af[mt][3], aBuf + aOff[mt] + kbB);
#pragma unroll
            for (int p = 0; p < 2; p++)
                LDSM_X4(bf[2*p][0], bf[2*p][1], bf[2*p+1][0], bf[2*p+1][1], bBuf + bOff[p] + kbB);
#pragma unroll
            for (int mt = 0; mt < 4; mt++)
#pragma unroll
                for (int nt = 0; nt < 4; nt++)
                    mma_f16(acc[mt][nt], af[mt], bf[nt]);
        }

        if (kt + 1 < KT) do_sts((kt + 1) & 1);
        __syncthreads();
    }

    // ---- epilogue ----
    float*  Cf = (float*) Cv + (long)b * sC;
    __half* Ch = (__half*)Cv + (long)b * sC;
#pragma unroll
    for (int mt = 0; mt < 4; mt++) {
        const int r0 = mBlock + mw + mt * 16 + gr;
#pragma unroll
        for (int half_ = 0; half_ < 2; half_++) {
            const int row = r0 + half_ * 8;
            float rm = 1.0f; int mi = 1;
            if (mode == 1 && rowmask) rm = rowmask[(long)b * M + row] ? 1.0f : 0.0f;
            if (mode == 2) mi = m1p[(long)b * M + row];
#pragma unroll
            for (int nt = 0; nt < 4; nt++) {
                const int c0 = nBlock + nw + nt * 8 + tg * 2;
                float v0 = acc[mt][nt][half_ * 2 + 0];
                float v1 = acc[mt][nt][half_ * 2 + 1];
                if (mode == 1) {
                    v0 += bias[c0];     v1 += bias[c0 + 1];
                    v0 = (v0 >= 0.0f) ? v0 : SLOPE * v0;
                    v1 = (v1 >= 0.0f) ? v1 : SLOPE * v1;
                    v0 *= rm; v1 *= rm;
                } else if (mode == 2) {
                    const int mj0 = m2p[(long)b * N + c0];
                    const int mj1 = m2p[(long)b * N + c0 + 1];
                    v0 += (mi && mj0) ? 0.0f : NEG_INF_F;
                    v1 += (mi && mj1) ? 0.0f : NEG_INF_F;
                }
                if (outHalf) {
                    *(__half2*)&Ch[(long)row * ldC + c0] = __floats2half2_rn(v0, v1);
                } else {
                    float2 o; o.x = v0; o.y = v1;
                    *(float2*)&Cf[(long)row * ldC + c0] = o;
                }
            }
        }
    }
}

// ---------------- f32 -> f16 elementwise convert ----------------
__global__ __launch_bounds__(256)
void f2h_kernel(const float* __restrict__ src, __half* __restrict__ dst, int n)
{
    int i = (blockIdx.x * 256 + threadIdx.x) * 4;
    if (i < n) {
        float4 v = *(const float4*)(src + i);
        *(__half2*)(dst + i)     = __floats2half2_rn(v.x, v.y);
        *(__half2*)(dst + i + 2) = __floats2half2_rn(v.z, v.w);
    }
}

// ---------------- transpose f32 -> f16 (weights) ----------------
__global__ __launch_bounds__(256)
void transpose_f2h(const float* __restrict__ src, __half* __restrict__ dst,
                   int rows, int cols)
{
    __shared__ float t[32][33];
    const int x0 = blockIdx.x * 32;
    const int y0 = blockIdx.y * 32;
    const int tx = threadIdx.x, ty = threadIdx.y;
#pragma unroll
    for (int j = ty; j < 32; j += 8)
        t[j][tx] = src[(long)(y0 + j) * cols + x0 + tx];
    __syncthreads();
#pragma unroll
    for (int j = ty; j < 32; j += 8)
        dst[(long)(x0 + j) * rows + y0 + tx] = __float2half_rn(t[tx][j]);
}

// ---------------- batched transpose half -> half ----------------
__global__ __launch_bounds__(256)
void transpose_h(const __half* __restrict__ src, __half* __restrict__ dst,
                 int rows, int cols, long sS, long sD)
{
    __shared__ __half t[32][34];
    const __half* s = src + (long)blockIdx.z * sS;
    __half* d       = dst + (long)blockIdx.z * sD;
    const int x0 = blockIdx.x * 32;
    const int y0 = blockIdx.y * 32;
    const int tx = threadIdx.x, ty = threadIdx.y;
#pragma unroll
    for (int j = ty; j < 32; j += 8)
        t[j][tx] = s[(long)(y0 + j) * cols + x0 + tx];
    __syncthreads();
#pragma unroll
    for (int j = ty; j < 32; j += 8)
        d[(long)(x0 + j) * rows + y0 + tx] = t[tx][j];
}

// ---------------- Row softmax: o1 (half) = softmax_rows(S)*mpos ----------------
__global__ __launch_bounds__(256)
void softmax_row_kernel(const float* __restrict__ S, __half* __restrict__ O,
                        const int* __restrict__ m1, const int* __restrict__ m2)
{
    const int b = blockIdx.y, i = blockIdx.x;
    const float* row = S + ((long)b * Lc + i) * Lc;
    __half* orow     = O + ((long)b * Lc + i) * Lc;
    const int tid = threadIdx.x;

    float v0 = row[tid], v1 = row[tid + 256];
    __shared__ float red[256];

    red[tid] = fmaxf(v0, v1);
    __syncthreads();
    for (int s = 128; s > 0; s >>= 1) {
        if (tid < s) red[tid] = fmaxf(red[tid], red[tid + s]);
        __syncthreads();
    }
    float mx = red[0];
    __syncthreads();

    float e0 = __expf(v0 - mx), e1 = __expf(v1 - mx);
    red[tid] = e0 + e1;
    __syncthreads();
    for (int s = 128; s > 0; s >>= 1) {
        if (tid < s) red[tid] += red[tid + s];
        __syncthreads();
    }
    float inv = 1.0f / red[0];

    int mi = m1[b * Lc + i];
    float f0 = (mi && m2[b * Lc + tid])       ? 1.0f : 0.0f;
    float f1 = (mi && m2[b * Lc + tid + 256]) ? 1.0f : 0.0f;
    orow[tid]       = __float2half_rn(e0 * inv * f0);
    orow[tid + 256] = __float2half_rn(e1 * inv * f1);
}

// -------- Column softmax, writes TRANSPOSED half result --------
__global__ __launch_bounds__(1024)
void softmax_col_kernel(const float* __restrict__ S, __half* __restrict__ OT,
                        const int* __restrict__ m1, const int* __restrict__ m2)
{
    const int b  = blockIdx.y;
    const int tx = threadIdx.x, ty = threadIdx.y;   // 32x32
    const int j  = blockIdx.x * 32 + tx;
    const float* Sb = S  + (long)b * Lc * Lc;
    __half* OTb     = OT + (long)b * Lc * Lc;

    float vals[16];
    float lmax = -1e30f;
#pragma unroll
    for (int it = 0; it < 16; it++) {
        int i = ty + it * 32;
        vals[it] = Sb[(long)i * Lc + j];
        lmax = fmaxf(lmax, vals[it]);
    }
    __shared__ float red[32][33];
    red[ty][tx] = lmax;
    __syncthreads();
    for (int s = 16; s > 0; s >>= 1) {
        if (ty < s) red[ty][tx] = fmaxf(red[ty][tx], red[ty + s][tx]);
        __syncthreads();
    }
    float mx = red[0][tx];
    __syncthreads();

    float lsum = 0.0f;
#pragma unroll
    for (int it = 0; it < 16; it++) {
        vals[it] = __expf(vals[it] - mx);
        lsum += vals[it];
    }
    red[ty][tx] = lsum;
    __syncthreads();
    for (int s = 16; s > 0; s >>= 1) {
        if (ty < s) red[ty][tx] += red[ty + s][tx];
        __syncthreads();
    }
    float inv = 1.0f / red[0][tx];
    __syncthreads();

    const int mj = m2[b * Lc + j];
    const int j0 = blockIdx.x * 32;
#pragma unroll
    for (int it = 0; it < 16; it++) {
        int i = ty + it * 32;
        float f = (mj && m1[b * Lc + i]) ? 1.0f : 0.0f;
        float v = vals[it] * inv * f;
        red[ty][tx] = v;
        __syncthreads();
        OTb[(long)(j0 + ty) * Lc + it * 32 + tx] = __float2half_rn(red[tx][ty]);
        __syncthreads();
    }
}

// ---------------- Launch ----------------
extern "C" void kernel_launch(void* const* d_in, const int* in_sizes, int n_in,
                              void* d_out, int out_size)
{
    const float* r1    = (const float*)d_in[0];
    const float* r2    = (const float*)d_in[1];
    const int*   mask1 = (const int*)  d_in[2];
    const int*   mask2 = (const int*)  d_in[3];
    const float* W1    = (const float*)d_in[4];
    const float* b1    = (const float*)d_in[5];
    const float* W2    = (const float*)d_in[6];
    const float* b2    = (const float*)d_in[7];
    const float* Wc1   = (const float*)d_in[8];   // [1024, 512]
    const float* bc1   = (const float*)d_in[9];
    const float* Wc2   = (const float*)d_in[10];
    const float* bc2   = (const float*)d_in[11];
    float* out = (float*)d_out;

    __half *r1h, *r2h, *hh, *r1mh, *r2mh, *r1mTh, *r2mTh, *o1h, *o2Th, *c1h, *c2h;
    __half *W1Th, *W2Th, *Wc1Th, *Wc2Th;
    float *S;
    cudaGetSymbolAddress((void**)&r1h,   g_r1h);
    cudaGetSymbolAddress((void**)&r2h,   g_r2h);
    cudaGetSymbolAddress((void**)&hh,    g_hh);
    cudaGetSymbolAddress((void**)&r1mh,  g_r1mh);
    cudaGetSymbolAddress((void**)&r2mh,  g_r2mh);
    cudaGetSymbolAddress((void**)&r1mTh, g_r1mTh);
    cudaGetSymbolAddress((void**)&r2mTh, g_r2mTh);
    cudaGetSymbolAddress((void**)&o1h,   g_o1h);
    cudaGetSymbolAddress((void**)&o2Th,  g_o2Th);
    cudaGetSymbolAddress((void**)&c1h,   g_c1h);
    cudaGetSymbolAddress((void**)&c2h,   g_c2h);
    cudaGetSymbolAddress((void**)&W1Th,  g_W1Th);
    cudaGetSymbolAddress((void**)&W2Th,  g_W2Th);
    cudaGetSymbolAddress((void**)&Wc1Th, g_Wc1Th);
    cudaGetSymbolAddress((void**)&Wc2Th, g_Wc2Th);
    cudaGetSymbolAddress((void**)&S,     g_S);

    const long LD = (long)Lc * Dc;   // 262144
    dim3 blk(256);
    dim3 gridMlp(Dc / BN, (Bc * Lc) / BM, 1);   // (4, 256, 1)
    dim3 gridBat(Dc / BN, Lc / BM, Bc);         // (4, 4, 64)
    dim3 tblk(32, 8);

    // ---- convert inputs to half ----
    f2h_kernel<<<BLD / 4 / 256, 256>>>(r1, r1h, BLD);
    f2h_kernel<<<BLD / 4 / 256, 256>>>(r2, r2h, BLD);

    // ---- transpose weights to half (K-contiguous B operands) ----
    transpose_f2h<<<dim3(Dc/32, Dc/32), tblk>>>(W1,  W1Th,  Dc,   Dc);
    transpose_f2h<<<dim3(Dc/32, Dc/32), tblk>>>(W2,  W2Th,  Dc,   Dc);
    transpose_f2h<<<dim3(Dc/32, 2*Dc/32), tblk>>>(Wc1, Wc1Th, 2*Dc, Dc);
    transpose_f2h<<<dim3(Dc/32, Dc/32), tblk>>>(Wc2, Wc2Th, Dc,   Dc);

    // ---- MLP r1 ----
    gemm_h<<<gridMlp, blk>>>(r1h, r1h, W1Th, hh,
        Bc*Lc, Dc, Dc, 0, Dc, Dc, Dc, Dc, 0, 0, 0, 0,
        b1, nullptr, nullptr, nullptr, 1, 1);
    gemm_h<<<gridMlp, blk>>>(hh, hh, W2Th, r1mh,
        Bc*Lc, Dc, Dc, 0, Dc, Dc, Dc, Dc, 0, 0, 0, 0,
        b2, mask1, nullptr, nullptr, 1, 1);
    // ---- MLP r2 ----
    gemm_h<<<gridMlp, blk>>>(r2h, r2h, W1Th, hh,
        Bc*Lc, Dc, Dc, 0, Dc, Dc, Dc, Dc, 0, 0, 0, 0,
        b1, nullptr, nullptr, nullptr, 1, 1);
    gemm_h<<<gridMlp, blk>>>(hh, hh, W2Th, r2mh,
        Bc*Lc, Dc, Dc, 0, Dc, Dc, Dc, Dc, 0, 0, 0, 0,
        b2, mask2, nullptr, nullptr, 1, 1);

    // ---- Scores: S (float) = r1m @ r2m^T + mask ----
    gemm_h<<<dim3(Lc/BN, Lc/BM, Bc), blk>>>(r1mh, r1mh, r2mh, S,
        Lc, Lc, Dc, 0, Dc, Dc, Dc, Lc, LD, LD, LD, LD,
        nullptr, nullptr, mask1, mask2, 2, 0);

    // ---- Softmaxes (half outputs; col writes o2^T) ----
    softmax_col_kernel<<<dim3(Lc/32, Bc), dim3(32, 32)>>>(S, o2Th, mask1, mask2);
    softmax_row_kernel<<<dim3(Lc, Bc), 256>>>(S, o1h, mask1, mask2);

    // ---- transpose activations for value GEMMs (half) ----
    transpose_h<<<dim3(Dc/32, Lc/32, Bc), tblk>>>(r1mh, r1mTh, Lc, Dc, LD, LD);
    transpose_h<<<dim3(Dc/32, Lc/32, Bc), tblk>>>(r2mh, r2mTh, Lc, Dc, LD, LD);

    // ---- r1c = o1 @ r2m ----
    gemm_h<<<gridBat, blk>>>(o1h, o1h, r2mTh, c1h,
        Lc, Dc, Lc, 0, Lc, Lc, Lc, Dc, LD, LD, LD, LD,
        nullptr, nullptr, nullptr, nullptr, 0, 1);
    // ---- r2c = o2^T @ r1m ----
    gemm_h<<<gridBat, blk>>>(o2Th, o2Th, r1mTh, c2h,
        Lc, Dc, Lc, 0, Lc, Lc, Lc, Dc, LD, LD, LD, LD,
        nullptr, nullptr, nullptr, nullptr, 0, 1);

    // ---- Compare r1: [r1m | c1] @ Wc1T (K=1024), then @ Wc2T -> out (f32) ----
    gemm_h<<<gridMlp, blk>>>(r1mh, c1h, Wc1Th, hh,
        Bc*Lc, Dc, 2*Dc, Dc, Dc, Dc, 2*Dc, Dc, 0, 0, 0, 0,
        bc1, nullptr, nullptr, nullptr, 1, 1);
    gemm_h<<<gridMlp, blk>>>(hh, hh, Wc2Th, out,
        Bc*Lc, Dc, Dc, 0, Dc, Dc, Dc, Dc, 0, 0, 0, 0,
        bc2, mask1, nullptr, nullptr, 1, 0);

    // ---- Compare r2 ----
    gemm_h<<<gridMlp, blk>>>(r2mh, c2h, Wc1Th, hh,
        Bc*Lc, Dc, 2*Dc, Dc, Dc, Dc, 2*Dc, Dc, 0, 0, 0, 0,
        bc1, nullptr, nullptr, nullptr, 1, 1);
    gemm_h<<<gridMlp, blk>>>(hh, hh, Wc2Th, out + (long)BLD,
        Bc*Lc, Dc, Dc, 0, Dc, Dc, Dc, Dc, 0, 0, 0, 0,
        bc2, mask2, nullptr, nullptr, 1, 0);
}

// round 13
// speedup vs baseline: 2.8954x; 1.1016x over previous
#include <cuda_runtime.h>
#include <cuda_fp16.h>
#include <cstdint>

// InterAttention (ESIM-style) on GB300 — fp16 mma.sync + ldmatrix + cp.async
// 4-stage pipeline, fused r1/r2 launches (wave-tail elimination).
// fp16 intermediates end-to-end; only S (softmax logits) and final outputs f32.

#define NEG_INF_F (-1e10f)
#define SLOPE 0.01f
#define Bc 64
#define Lc 512
#define Dc 512
#define BLD (Bc*Lc*Dc)

// ---- scratch: concatenated r1|r2 halves ----
__device__ __half g_rh  [2*BLD];   // r1h | r2h
__device__ __half g_hh  [2*BLD];   // hidden
__device__ __half g_rmh [2*BLD];   // r1m | r2m
__device__ __half g_rmTh[2*BLD];   // r2mT | r1mT   (value-GEMM B order)
__device__ __half g_oh  [2*BLD];   // o1  | o2T    (value-GEMM A order)
__device__ __half g_ch  [2*BLD];   // c1  | c2
__device__ __half g_W1Th[Dc*Dc];
__device__ __half g_W2Th[Dc*Dc];
__device__ __half g_Wc1Th[2*Dc*Dc];
__device__ __half g_Wc2Th[Dc*Dc];
__device__ float  g_S[BLD];

__device__ __forceinline__ void mma_f16(float* c, const uint32_t* a, const uint32_t* b) {
    asm volatile(
        "mma.sync.aligned.m16n8k16.row.col.f32.f16.f16.f32 "
        "{%0,%1,%2,%3}, {%4,%5,%6,%7}, {%8,%9}, {%0,%1,%2,%3};"
        : "+f"(c[0]), "+f"(c[1]), "+f"(c[2]), "+f"(c[3])
        : "r"(a[0]), "r"(a[1]), "r"(a[2]), "r"(a[3]), "r"(b[0]), "r"(b[1]));
}
#define LDSM_X4(r0, r1, r2, r3, addr) \
    asm volatile("ldmatrix.sync.aligned.m8n8.x4.shared.b16 {%0,%1,%2,%3}, [%4];" \
        : "=r"(r0), "=r"(r1), "=r"(r2), "=r"(r3) : "r"(addr))
#define CP_ASYNC16(saddr, gptr) \
    asm volatile("cp.async.cg.shared.global [%0], [%1], 16;" :: "r"(saddr), "l"(gptr) : "memory")
#define CP_COMMIT() asm volatile("cp.async.commit_group;" ::: "memory")
#define CP_WAIT2()  asm volatile("cp.async.wait_group 2;" ::: "memory")

__device__ __forceinline__ uint32_t smem_u32(const void* p){
    uint32_t a;
    asm("{ .reg .u64 t; cvta.to.shared.u64 t, %1; cvt.u32.u64 %0, t; }":"=r"(a):"l"(p));
    return a;
}

// ---------------- fp16 GEMM: cp.async 4-stage + ldmatrix ----------------
// C[b][m][n] = epilogue( sum_k opA[b][m][k]*opB[b][n][k] ); A,B half K-contig.
// Concat-K via A2/Ksplit. mode 0 plain; 1 bias+lrelu+rowmask (rowmask2/Mhalf
// selects second mask for fused r1|r2 launches); 2 score mask (f32 out).
#define BM 128
#define BN 128
#define BKH 32
#define SWH 40           // 80B row stride: 16B-aligned, conflict-free ldmatrix
#define STAGES 4
#define ASTG (BM*SWH)                    // halves per A stage
#define BSTG (BN*SWH)
#define GSMEM (STAGES*(ASTG+BSTG)*2)     // 81920 B dynamic

__global__ __launch_bounds__(256, 2)
void gemm_h(const __half* __restrict__ A, const __half* __restrict__ A2,
            const __half* __restrict__ B, void* __restrict__ Cv,
            int M, int N, int K, int Ksplit,
            int ldA, int ldA2, int ldB, int ldC,
            long sA, long sA2, long sB, long sC,
            const float* __restrict__ bias,
            const int* __restrict__ rowmask, const int* __restrict__ rowmask2,
            int Mhalf,
            const int* __restrict__ m1p, const int* __restrict__ m2p,
            int mode, int outHalf)
{
    extern __shared__ __half smem[];
    __half* As = smem;                    // [STAGES][BM][SWH]
    __half* Bs = smem + STAGES*ASTG;      // [STAGES][BN][SWH]

    const int b = blockIdx.z;
    const __half* Ab  = A  + (long)b * sA;
    const __half* A2b = A2 + (long)b * sA2;
    const __half* Bb  = B  + (long)b * sB;

    const int tid = threadIdx.x;
    const int mBlock = blockIdx.y * BM;
    const int nBlock = blockIdx.x * BN;

    // tile-load mapping: 4 threads/row (16B each), 64 rows/pass, 2 passes
    const int lrow = tid >> 2;
    const int lc8  = (tid & 3) * 8;

    // warp mapping: 8 warps 2(m) x 4(n); warp tile 64x32
    const int warp = tid >> 5, lane = tid & 31;
    const int mw = (warp >> 2) * 64;
    const int nw = (warp & 3) * 32;
    const int gr = lane >> 2;
    const int tg = lane & 3;

    const uint32_t aBase = smem_u32(As);
    const uint32_t bBase = smem_u32(Bs);
    uint32_t aOff[4], bOff[2];
    {
        const int g = lane >> 3;
#pragma unroll
        for (int mt = 0; mt < 4; mt++)
            aOff[mt] = (uint32_t)(((mw + mt * 16 + (lane & 15)) * SWH + (lane >> 4) * 8) * 2);
#pragma unroll
        for (int p = 0; p < 2; p++)
            bOff[p] = (uint32_t)(((nw + (p * 2 + (g >> 1)) * 8 + (lane & 7)) * SWH + (g & 1) * 8) * 2);
    }
    // per-thread STS targets (half-index within a stage)
    const uint32_t aStsBase = aBase + (uint32_t)((lrow * SWH + lc8) * 2);
    const uint32_t bStsBase = bBase + (uint32_t)((lrow * SWH + lc8) * 2);

    float acc[4][4][4];
#pragma unroll
    for (int i = 0; i < 4; i++)
#pragma unroll
        for (int j = 0; j < 4; j++)
#pragma unroll
            for (int q = 0; q < 4; q++) acc[i][j][q] = 0.0f;

    const int KT = K / BKH;

    auto issue = [&](int kt, int stg) {
        const int k0 = kt * BKH;
        const __half* Ap; int kb, ld;
        if (k0 < Ksplit) { Ap = Ab;  kb = k0;          ld = ldA;  }
        else             { Ap = A2b; kb = k0 - Ksplit; ld = ldA2; }
        const uint32_t sa = aStsBase + (uint32_t)(stg * ASTG * 2);
        const uint32_t sb = bStsBase + (uint32_t)(stg * BSTG * 2);
#pragma unroll
        for (int p = 0; p < 2; p++) {
            const int r = lrow + p * 64;
            CP_ASYNC16(sa + (uint32_t)(p * 64 * SWH * 2),
                       Ap + (long)(mBlock + r) * ld  + kb + lc8);
            CP_ASYNC16(sb + (uint32_t)(p * 64 * SWH * 2),
                       Bb + (long)(nBlock + r) * ldB + k0 + lc8);
        }
    };

    // prologue: stages 0..2
#pragma unroll
    for (int s = 0; s < STAGES - 1; s++) { issue(s, s); CP_COMMIT(); }

    for (int kt = 0; kt < KT; kt++) {
        CP_WAIT2();
        __syncthreads();
        if (kt + STAGES - 1 < KT) issue(kt + STAGES - 1, (kt + STAGES - 1) & (STAGES - 1));
        CP_COMMIT();

        const int buf = kt & (STAGES - 1);
        const uint32_t aBuf = aBase + (uint32_t)(buf * ASTG * 2);
        const uint32_t bBuf = bBase + (uint32_t)(buf * BSTG * 2);
#pragma unroll
        for (int ks = 0; ks < 2; ks++) {
            const uint32_t kbB = ks * 32;
            uint32_t af[4][4], bf[4][2];
#pragma unroll
            for (int mt = 0; mt < 4; mt++)
                LDSM_X4(af[mt][0], af[mt][1], af[mt][2], af[mt][3], aBuf + aOff[mt] + kbB);
#pragma unroll
            for (int p = 0; p < 2; p++)
                LDSM_X4(bf[2*p][0], bf[2*p][1], bf[2*p+1][0], bf[2*p+1][1], bBuf + bOff[p] + kbB);
#pragma unroll
            for (int mt = 0; mt < 4; mt++)
#pragma unroll
                for (int nt = 0; nt < 4; nt++)
                    mma_f16(acc[mt][nt], af[mt], bf[nt]);
        }
    }

    // ---- epilogue ----
    float*  Cf = (float*) Cv + (long)b * sC;
    __half* Ch = (__half*)Cv + (long)b * sC;
#pragma unroll
    for (int mt = 0; mt < 4; mt++) {
        const int r0 = mBlock + mw + mt * 16 + gr;
#pragma unroll
        for (int half_ = 0; half_ < 2; half_++) {
            const int row = r0 + half_ * 8;
            float rm = 1.0f; int mi = 1;
            if (mode == 1 && rowmask) {
                const int useB = (rowmask2 != nullptr) && (row >= Mhalf);
                const int* rmp = useB ? rowmask2 : rowmask;
                const int rr = useB ? row - Mhalf : row;
                rm = rmp[rr] ? 1.0f : 0.0f;
            }
            if (mode == 2) mi = m1p[(long)b * M + row];
#pragma unroll
            for (int nt = 0; nt < 4; nt++) {
                const int c0 = nBlock + nw + nt * 8 + tg * 2;
                float v0 = acc[mt][nt][half_ * 2 + 0];
                float v1 = acc[mt][nt][half_ * 2 + 1];
                if (mode == 1) {
                    v0 += bias[c0];     v1 += bias[c0 + 1];
                    v0 = (v0 >= 0.0f) ? v0 : SLOPE * v0;
                    v1 = (v1 >= 0.0f) ? v1 : SLOPE * v1;
                    v0 *= rm; v1 *= rm;
                } else if (mode == 2) {
                    const int mj0 = m2p[(long)b * N + c0];
                    const int mj1 = m2p[(long)b * N + c0 + 1];
                    v0 += (mi && mj0) ? 0.0f : NEG_INF_F;
                    v1 += (mi && mj1) ? 0.0f : NEG_INF_F;
                }
                if (outHalf) {
                    *(__half2*)&Ch[(long)row * ldC + c0] = __floats2half2_rn(v0, v1);
                } else {
                    float2 o; o.x = v0; o.y = v1;
                    *(float2*)&Cf[(long)row * ldC + c0] = o;
                }
            }
        }
    }
}

// ---------------- f32 -> f16 elementwise convert ----------------
__global__ __launch_bounds__(256)
void f2h_kernel(const float* __restrict__ src, __half* __restrict__ dst, int n)
{
    int i = (blockIdx.x * 256 + threadIdx.x) * 4;
    if (i < n) {
        float4 v = *(const float4*)(src + i);
        *(__half2*)(dst + i)     = __floats2half2_rn(v.x, v.y);
        *(__half2*)(dst + i + 2) = __floats2half2_rn(v.z, v.w);
    }
}

// ---------------- transpose f32 -> f16 (weights) ----------------
__global__ __launch_bounds__(256)
void transpose_f2h(const float* __restrict__ src, __half* __restrict__ dst,
                   int rows, int cols)
{
    __shared__ float t[32][33];
    const int x0 = blockIdx.x * 32;
    const int y0 = blockIdx.y * 32;
    const int tx = threadIdx.x, ty = threadIdx.y;
#pragma unroll
    for (int j = ty; j < 32; j += 8)
        t[j][tx] = src[(long)(y0 + j) * cols + x0 + tx];
    __syncthreads();
#pragma unroll
    for (int j = ty; j < 32; j += 8)
        dst[(long)(x0 + j) * rows + y0 + tx] = __float2half_rn(t[tx][j]);
}

// ---------------- batched transpose half -> half ----------------
__global__ __launch_bounds__(256)
void transpose_h(const __half* __restrict__ src, __half* __restrict__ dst,
                 int rows, int cols, long sS, long sD)
{
    __shared__ __half t[32][34];
    const __half* s = src + (long)blockIdx.z * sS;
    __half* d       = dst + (long)blockIdx.z * sD;
    const int x0 = blockIdx.x * 32;
    const int y0 = blockIdx.y * 32;
    const int tx = threadIdx.x, ty = threadIdx.y;
#pragma unroll
    for (int j = ty; j < 32; j += 8)
        t[j][tx] = s[(long)(y0 + j) * cols + x0 + tx];
    __syncthreads();
#pragma unroll
    for (int j = ty; j < 32; j += 8)
        d[(long)(x0 + j) * rows + y0 + tx] = t[tx][j];
}

// ---------------- Row softmax ----------------
__global__ __launch_bounds__(256)
void softmax_row_kernel(const float* __restrict__ S, __half* __restrict__ O,
                        const int* __restrict__ m1, const int* __restrict__ m2)
{
    const int b = blockIdx.y, i = blockIdx.x;
    const float* row = S + ((long)b * Lc + i) * Lc;
    __half* orow     = O + ((long)b * Lc + i) * Lc;
    const int tid = threadIdx.x;

    float v0 = row[tid], v1 = row[tid + 256];
    __shared__ float red[256];

    red[tid] = fmaxf(v0, v1);
    __syncthreads();
    for (int s = 128; s > 0; s >>= 1) {
        if (tid < s) red[tid] = fmaxf(red[tid], red[tid + s]);
        __syncthreads();
    }
    float mx = red[0];
    __syncthreads();

    float e0 = __expf(v0 - mx), e1 = __expf(v1 - mx);
    red[tid] = e0 + e1;
    __syncthreads();
    for (int s = 128; s > 0; s >>= 1) {
        if (tid < s) red[tid] += red[tid + s];
        __syncthreads();
    }
    float inv = 1.0f / red[0];

    int mi = m1[b * Lc + i];
    float f0 = (mi && m2[b * Lc + tid])       ? 1.0f : 0.0f;
    float f1 = (mi && m2[b * Lc + tid + 256]) ? 1.0f : 0.0f;
    orow[tid]       = __float2half_rn(e0 * inv * f0);
    orow[tid + 256] = __float2half_rn(e1 * inv * f1);
}

// -------- Column softmax, writes TRANSPOSED half result --------
__global__ __launch_bounds__(1024)
void softmax_col_kernel(const float* __restrict__ S, __half* __restrict__ OT,
                        const int* __restrict__ m1, const int* __restrict__ m2)
{
    const int b  = blockIdx.y;
    const int tx = threadIdx.x, ty = threadIdx.y;
    const int j  = blockIdx.x * 32 + tx;
    const float* Sb = S  + (long)b * Lc * Lc;
    __half* OTb     = OT + (long)b * Lc * Lc;

    float vals[16];
    float lmax = -1e30f;
#pragma unroll
    for (int it = 0; it < 16; it++) {
        int i = ty + it * 32;
        vals[it] = Sb[(long)i * Lc + j];
        lmax = fmaxf(lmax, vals[it]);
    }
    __shared__ float red[32][33];
    red[ty][tx] = lmax;
    __syncthreads();
    for (int s = 16; s > 0; s >>= 1) {
        if (ty < s) red[ty][tx] = fmaxf(red[ty][tx], red[ty + s][tx]);
        __syncthreads();
    }
    float mx = red[0][tx];
    __syncthreads();

    float lsum = 0.0f;
#pragma unroll
    for (int it = 0; it < 16; it++) {
        vals[it] = __expf(vals[it] - mx);
        lsum += vals[it];
    }
    red[ty][tx] = lsum;
    __syncthreads();
    for (int s = 16; s > 0; s >>= 1) {
        if (ty < s) red[ty][tx] += red[ty + s][tx];
        __syncthreads();
    }
    float inv = 1.0f / red[0][tx];
    __syncthreads();

    const int mj = m2[b * Lc + j];
    const int j0 = blockIdx.x * 32;
#pragma unroll
    for (int it = 0; it < 16; it++) {
        int i = ty + it * 32;
        float f = (mj && m1[b * Lc + i]) ? 1.0f : 0.0f;
        float v = vals[it] * inv * f;
        red[ty][tx] = v;
        __syncthreads();
        OTb[(long)(j0 + ty) * Lc + it * 32 + tx] = __float2half_rn(red[tx][ty]);
        __syncthreads();
    }
}

// ---------------- Launch ----------------
extern "C" void kernel_launch(void* const* d_in, const int* in_sizes, int n_in,
                              void* d_out, int out_size)
{
    const float* r1    = (const float*)d_in[0];
    const float* r2    = (const float*)d_in[1];
    const int*   mask1 = (const int*)  d_in[2];
    const int*   mask2 = (const int*)  d_in[3];
    const float* W1    = (const float*)d_in[4];
    const float* b1    = (const float*)d_in[5];
    const float* W2    = (const float*)d_in[6];
    const float* b2    = (const float*)d_in[7];
    const float* Wc1   = (const float*)d_in[8];
    const float* bc1   = (const float*)d_in[9];
    const float* Wc2   = (const float*)d_in[10];
    const float* bc2   = (const float*)d_in[11];
    float* out = (float*)d_out;

    __half *rh, *hh, *rmh, *rmTh, *oh, *ch, *W1Th, *W2Th, *Wc1Th, *Wc2Th;
    float *S;
    cudaGetSymbolAddress((void**)&rh,    g_rh);
    cudaGetSymbolAddress((void**)&hh,    g_hh);
    cudaGetSymbolAddress((void**)&rmh,   g_rmh);
    cudaGetSymbolAddress((void**)&rmTh,  g_rmTh);
    cudaGetSymbolAddress((void**)&oh,    g_oh);
    cudaGetSymbolAddress((void**)&ch,    g_ch);
    cudaGetSymbolAddress((void**)&W1Th,  g_W1Th);
    cudaGetSymbolAddress((void**)&W2Th,  g_W2Th);
    cudaGetSymbolAddress((void**)&Wc1Th, g_Wc1Th);
    cudaGetSymbolAddress((void**)&Wc2Th, g_Wc2Th);
    cudaGetSymbolAddress((void**)&S,     g_S);

    cudaFuncSetAttribute(gemm_h, cudaFuncAttributeMaxDynamicSharedMemorySize, GSMEM);

    const long LD = (long)Lc * Dc;   // 262144
    const int  M2 = 2 * Bc * Lc;     // 65536 (r1|r2 fused)
    dim3 blk(256);
    dim3 gridFused(Dc / BN, M2 / BM, 1);        // (4, 512)
    dim3 gridVal(Dc / BN, Lc / BM, 2 * Bc);     // (4, 4, 128)
    dim3 tblk(32, 8);

    // ---- inputs -> half (concatenated) ----
    f2h_kernel<<<BLD / 4 / 256, 256>>>(r1, rh,        BLD);
    f2h_kernel<<<BLD / 4 / 256, 256>>>(r2, rh + BLD,  BLD);

    // ---- weights -> half, transposed ----
    transpose_f2h<<<dim3(Dc/32, Dc/32), tblk>>>(W1,  W1Th,  Dc,   Dc);
    transpose_f2h<<<dim3(Dc/32, Dc/32), tblk>>>(W2,  W2Th,  Dc,   Dc);
    transpose_f2h<<<dim3(Dc/32, 2*Dc/32), tblk>>>(Wc1, Wc1Th, 2*Dc, Dc);
    transpose_f2h<<<dim3(Dc/32, Dc/32), tblk>>>(Wc2, Wc2Th, Dc,   Dc);

    // ---- MLP layer 1 (r1|r2 fused) ----
    gemm_h<<<gridFused, blk, GSMEM>>>(rh, rh, W1Th, hh,
        M2, Dc, Dc, 0, Dc, Dc, Dc, Dc, 0, 0, 0, 0,
        b1, nullptr, nullptr, 0, nullptr, nullptr, 1, 1);
    // ---- MLP layer 2 (rowmask split mask1/mask2) ----
    gemm_h<<<gridFused, blk, GSMEM>>>(hh, hh, W2Th, rmh,
        M2, Dc, Dc, 0, Dc, Dc, Dc, Dc, 0, 0, 0, 0,
        b2, mask1, mask2, Bc*Lc, nullptr, nullptr, 1, 1);

    // ---- Scores: S (f32) = r1m @ r2m^T + mask ----
    gemm_h<<<dim3(Lc/BN, Lc/BM, Bc), blk, GSMEM>>>(rmh, rmh, rmh + BLD, S,
        Lc, Lc, Dc, 0, Dc, Dc, Dc, Lc, LD, LD, LD, LD,
        nullptr, nullptr, nullptr, 0, mask1, mask2, 2, 0);

    // ---- Softmaxes -> oh = [o1 | o2T] ----
    softmax_col_kernel<<<dim3(Lc/32, Bc), dim3(32, 32)>>>(S, oh + BLD, mask1, mask2);
    softmax_row_kernel<<<dim3(Lc, Bc), 256>>>(S, oh, mask1, mask2);

    // ---- activation transposes -> rmTh = [r2mT | r1mT] ----
    transpose_h<<<dim3(Dc/32, Lc/32, Bc), tblk>>>(rmh + BLD, rmTh,       Lc, Dc, LD, LD);
    transpose_h<<<dim3(Dc/32, Lc/32, Bc), tblk>>>(rmh,       rmTh + BLD, Lc, Dc, LD, LD);

    // ---- value GEMMs fused (z=128): ch = [c1 | c2] ----
    gemm_h<<<gridVal, blk, GSMEM>>>(oh, oh, rmTh, ch,
        Lc, Dc, Lc, 0, Lc, Lc, Lc, Dc, LD, LD, LD, LD,
        nullptr, nullptr, nullptr, 0, nullptr, nullptr, 0, 1);

    // ---- Compare layer 1 fused: [rm | c] @ Wc1T (K=1024) ----
    gemm_h<<<gridFused, blk, GSMEM>>>(rmh, ch, Wc1Th, hh,
        M2, Dc, 2*Dc, Dc, Dc, Dc, 2*Dc, Dc, 0, 0, 0, 0,
        bc1, nullptr, nullptr, 0, nullptr, nullptr, 1, 1);
    // ---- Compare layer 2 fused -> out (f32, contiguous r1|r2) ----
    gemm_h<<<gridFused, blk, GSMEM>>>(hh, hh, Wc2Th, out,
        M2, Dc, Dc, 0, Dc, Dc, Dc, Dc, 0, 0, 0, 0,
        bc2, mask1, mask2, Bc*Lc, nullptr, nullptr, 1, 0);
}